// round 14
// baseline (speedup 1.0000x reference)
#include <cuda_runtime.h>
#include <cuda_bf16.h>
#include <math.h>
#include <stdint.h>

#define Bc 4
#define Tc 1024
#define Dc 1024
#define Hc 16
#define DHc 64
#define Mrows (Bc*Tc)          // 4096
#define BHc (Bc*Hc)            // 64

// ---------------- static scratch (no allocations allowed) ----------------
__device__ float g_q[Mrows*Dc];
__device__ float g_k[Mrows*Dc];
__device__ float g_vt[BHc*DHc*Tc];     // V transposed per (b,h): [d][T] (tf32 bits)
__device__ float g_att[Mrows*Dc];
__device__ float g_h1[Mrows*Dc];
__device__ float g_f2[Mrows*Dc];
__device__ uint32_t g_xb[Mrows*Dc/2];  // x as bf16 pairs
__device__ uint32_t g_wb[5*Dc*Dc/2];   // transposed weights as bf16
__device__ uint32_t g_h1b[Mrows*Dc/2];
__device__ uint32_t g_f1b[Mrows*Dc/2];

__device__ __forceinline__ uint32_t f2tf32(float f) {
    uint32_t r;
    asm("cvt.rna.tf32.f32 %0, %1;" : "=r"(r) : "f"(f));
    return r;
}
__device__ __forceinline__ uint32_t pack_bf16x2(float lo, float hi) {
    uint32_t r;
    asm("cvt.rn.bf16x2.f32 %0, %1, %2;" : "=r"(r) : "f"(hi), "f"(lo));
    return r;
}
__device__ __forceinline__ uint32_t smem_u32(const void* p) {
    uint32_t a;
    asm("{ .reg .u64 t; cvta.to.shared.u64 t, %1; cvt.u32.u64 %0, t; }" : "=r"(a) : "l"(p));
    return a;
}
__device__ __forceinline__ void mma_tf32(float& d0, float& d1, float& d2, float& d3,
                                         uint32_t a0, uint32_t a1, uint32_t a2, uint32_t a3,
                                         uint32_t b0, uint32_t b1) {
    asm volatile(
        "mma.sync.aligned.m16n8k8.row.col.f32.tf32.tf32.f32 "
        "{%0,%1,%2,%3},{%4,%5,%6,%7},{%8,%9},{%0,%1,%2,%3};"
        : "+f"(d0), "+f"(d1), "+f"(d2), "+f"(d3)
        : "r"(a0), "r"(a1), "r"(a2), "r"(a3), "r"(b0), "r"(b1));
}
__device__ __forceinline__ void mma_bf16(float& d0, float& d1, float& d2, float& d3,
                                         uint32_t a0, uint32_t a1, uint32_t a2, uint32_t a3,
                                         uint32_t b0, uint32_t b1) {
    asm volatile(
        "mma.sync.aligned.m16n8k16.row.col.f32.bf16.bf16.f32 "
        "{%0,%1,%2,%3},{%4,%5,%6,%7},{%8,%9},{%0,%1,%2,%3};"
        : "+f"(d0), "+f"(d1), "+f"(d2), "+f"(d3)
        : "r"(a0), "r"(a1), "r"(a2), "r"(a3), "r"(b0), "r"(b1));
}
__device__ __forceinline__ void ldsm_x4(uint32_t& r0, uint32_t& r1, uint32_t& r2,
                                        uint32_t& r3, uint32_t addr) {
    asm volatile("ldmatrix.sync.aligned.m8n8.x4.shared.b16 {%0,%1,%2,%3}, [%4];"
                 : "=r"(r0), "=r"(r1), "=r"(r2), "=r"(r3) : "r"(addr));
}
__device__ __forceinline__ void cp16(uint32_t dst, const void* src) {
    asm volatile("cp.async.cg.shared.global [%0], [%1], 16;" :: "r"(dst), "l"(src));
}
__device__ __forceinline__ void cp_commit() {
    asm volatile("cp.async.commit_group;");
}
template<int N>
__device__ __forceinline__ void cp_wait() {
    asm volatile("cp.async.wait_group %0;" :: "n"(N));
}
__device__ __forceinline__ uint32_t sw256(int row, int c) {
    return ((uint32_t)row << 8) + (((((c & 7) ^ (row & 7)) | (c & 8)) << 4));
}

// ========== merged pre-pass: weights -> transposed bf16, x -> bf16 =========
__global__ __launch_bounds__(256)
void prep(const float* __restrict__ x,
          const float* __restrict__ wq, const float* __restrict__ wk,
          const float* __restrict__ wv, const float* __restrict__ w1,
          const float* __restrict__ w2,
          uint32_t* __restrict__ xb, __nv_bfloat16* __restrict__ wb) {
    __shared__ float t[32][33];
    const int bx = blockIdx.x;
    if (bx < 5120) {
        const int seg = bx >> 10;
        const int within = bx & 1023;
        const int nb = (within & 31) * 32;
        const int kb = (within >> 5) * 32;
        const float* src = seg == 0 ? wq : seg == 1 ? wk : seg == 2 ? wv
                          : seg == 3 ? w1 : w2;
        __nv_bfloat16* dst = wb + (size_t)seg * Dc * Dc;
        const int tx = threadIdx.x & 31;
        const int ty = threadIdx.x >> 5;
        #pragma unroll
        for (int i = 0; i < 4; i++) {
            int k = kb + ty + i * 8;
            t[ty + i * 8][tx] = src[(size_t)k * Dc + nb + tx];
        }
        __syncthreads();
        #pragma unroll
        for (int i = 0; i < 4; i++) {
            int n = nb + ty + i * 8;
            dst[(size_t)n * Dc + kb + tx] = __float2bfloat16_rn(t[tx][ty + i * 8]);
        }
    } else {
        int i = (bx - 5120) * 256 + threadIdx.x;
        float4 v = reinterpret_cast<const float4*>(x)[i];
        xb[2 * i]     = pack_bf16x2(v.x, v.y);
        xb[2 * i + 1] = pack_bf16x2(v.z, v.w);
    }
}

// ================== cp.async + ldmatrix bf16 warp-MMA GEMM =================
#define GS 3
#define STAGE_BYTES 32768
#define GEMM2_SMEM (GS*STAGE_BYTES)    // 98304
#define KT2 16                          // 1024/64

template<bool RELU, bool BIAS, bool ROUND, bool TRANSV, bool OBF>
__global__ void __launch_bounds__(256, 2)
gemm_bf(const __nv_bfloat16* __restrict__ A,
        const __nv_bfloat16* __restrict__ W0, const __nv_bfloat16* __restrict__ W1,
        const __nv_bfloat16* __restrict__ W2,
        const float* __restrict__ bias,
        float* __restrict__ C0, float* __restrict__ C1, float* __restrict__ C2) {
    extern __shared__ uint32_t sm[];
    const uint32_t sbase = smem_u32(sm);
    const int tid = threadIdx.x;
    const int wid = tid >> 5, lane = tid & 31;
    const int warp_m = wid >> 2, warp_n = wid & 3;
    const int g = lane >> 2, tg = lane & 3;
    const int bm = blockIdx.y * 128, bn = blockIdx.x * 128;
    const int z = blockIdx.z;
    const __nv_bfloat16* W = z == 0 ? W0 : z == 1 ? W1 : W2;
    float* C = z == 0 ? C0 : z == 1 ? C1 : C2;
    const float oscale = (TRANSV && z == 0) ? 0.125f : 1.0f;

    float acc[4][4][4];
    #pragma unroll
    for (int i = 0; i < 4; i++)
        #pragma unroll
        for (int j = 0; j < 4; j++)
            #pragma unroll
            for (int r = 0; r < 4; r++) acc[i][j][r] = 0.f;

    const int arowoff = ((lane >> 3) & 1) * 8 + (lane & 7);
    const int acbit   = (lane >> 4) & 1;
    const int browoff = ((lane >> 4) & 1) * 8 + (lane & 7);
    const int bcbit   = (lane >> 3) & 1;

    auto issue = [&](int kt, int st) {
        uint32_t abase = sbase + st * STAGE_BYTES;
        uint32_t bbase = abase + 16384;
        #pragma unroll
        for (int i = 0; i < 4; i++) {
            int ca = tid + i * 256;
            int row = ca >> 3, c4 = ca & 7;
            uint32_t doff = row * 128 + ((c4 ^ (row & 7)) << 4);
            cp16(abase + doff, A + (size_t)(bm + row) * Dc + kt * 64 + c4 * 8);
            cp16(bbase + doff, W + (size_t)(bn + row) * Dc + kt * 64 + c4 * 8);
        }
    };

    auto compute = [&](int st) {
        uint32_t abase = sbase + st * STAGE_BYTES;
        uint32_t bbase = abase + 16384;
        #pragma unroll
        for (int s = 0; s < 4; s++) {
            uint32_t af[4][4];
            #pragma unroll
            for (int i = 0; i < 4; i++) {
                int row = warp_m * 64 + i * 16 + arowoff;
                uint32_t ad = abase + row * 128 + (((2 * s + acbit) ^ (row & 7)) << 4);
                ldsm_x4(af[i][0], af[i][1], af[i][2], af[i][3], ad);
            }
            uint32_t bf[4][2];
            #pragma unroll
            for (int jp = 0; jp < 2; jp++) {
                int row = warp_n * 32 + jp * 16 + browoff;
                uint32_t bd = bbase + row * 128 + (((2 * s + bcbit) ^ (row & 7)) << 4);
                ldsm_x4(bf[2 * jp][0], bf[2 * jp][1],
                        bf[2 * jp + 1][0], bf[2 * jp + 1][1], bd);
            }
            #pragma unroll
            for (int i = 0; i < 4; i++)
                #pragma unroll
                for (int j = 0; j < 4; j++)
                    mma_bf16(acc[i][j][0], acc[i][j][1], acc[i][j][2], acc[i][j][3],
                             af[i][0], af[i][1], af[i][2], af[i][3],
                             bf[j][0], bf[j][1]);
        }
    };

    issue(0, 0); cp_commit();
    issue(1, 1); cp_commit();
    for (int kt = 0; kt < KT2; kt++) {
        cp_wait<1>();
        __syncthreads();
        int nk = kt + 2;
        if (nk < KT2) issue(nk, nk - (nk / 3) * 3);
        cp_commit();
        compute(kt - (kt / 3) * 3);
    }
    cp_wait<0>();

    if (TRANSV && z == 2) {
        __syncthreads();
        float* sf = reinterpret_cast<float*>(sm);   // [128 n][132 pad] floats
        #pragma unroll
        for (int i = 0; i < 4; i++) {
            int ml = warp_m * 64 + i * 16 + g;
            #pragma unroll
            for (int j = 0; j < 4; j++) {
                int nl = warp_n * 32 + j * 8 + tg * 2;
                float v0 = acc[i][j][0], v1 = acc[i][j][1];
                float v2 = acc[i][j][2], v3 = acc[i][j][3];
                if (ROUND) {
                    v0 = __uint_as_float(f2tf32(v0));
                    v1 = __uint_as_float(f2tf32(v1));
                    v2 = __uint_as_float(f2tf32(v2));
                    v3 = __uint_as_float(f2tf32(v3));
                }
                sf[nl * 132 + ml]           = v0;
                sf[(nl + 1) * 132 + ml]     = v1;
                sf[nl * 132 + ml + 8]       = v2;
                sf[(nl + 1) * 132 + ml + 8] = v3;
            }
        }
        __syncthreads();
        const int b_ = bm >> 10;
        const int t0 = bm & 1023;
        #pragma unroll
        for (int it = 0; it < 16; it++) {
            int idx = tid + it * 256;
            int nl = idx >> 5, m4 = (idx & 31) << 2;
            float4 vv = *reinterpret_cast<float4*>(&sf[nl * 132 + m4]);
            int h_ = (bn + nl) >> 6, dd = (bn + nl) & 63;
            float* dst = C + ((size_t)((b_ << 4) + h_) * 64 + dd) * 1024 + t0 + m4;
            *reinterpret_cast<float4*>(dst) = vv;
        }
        return;
    }

    #pragma unroll
    for (int i = 0; i < 4; i++) {
        int m0 = bm + warp_m * 64 + i * 16 + g;
        #pragma unroll
        for (int j = 0; j < 4; j++) {
            int n0 = bn + warp_n * 32 + j * 8 + tg * 2;
            float v0 = acc[i][j][0], v1 = acc[i][j][1];
            float v2 = acc[i][j][2], v3 = acc[i][j][3];
            if (BIAS) {
                float b0v = bias[n0], b1v = bias[n0 + 1];
                v0 += b0v; v1 += b1v; v2 += b0v; v3 += b1v;
            }
            if (RELU) {
                v0 = fmaxf(v0, 0.f); v1 = fmaxf(v1, 0.f);
                v2 = fmaxf(v2, 0.f); v3 = fmaxf(v3, 0.f);
            }
            if (TRANSV) { v0 *= oscale; v1 *= oscale; v2 *= oscale; v3 *= oscale; }
            if (ROUND) {
                v0 = __uint_as_float(f2tf32(v0));
                v1 = __uint_as_float(f2tf32(v1));
                v2 = __uint_as_float(f2tf32(v2));
                v3 = __uint_as_float(f2tf32(v3));
            }
            if (OBF) {
                uint32_t* Cb = reinterpret_cast<uint32_t*>(C);
                Cb[((size_t)m0 * Dc + n0) >> 1] = pack_bf16x2(v0, v1);
                Cb[((size_t)(m0 + 8) * Dc + n0) >> 1] = pack_bf16x2(v2, v3);
            } else {
                *reinterpret_cast<float2*>(&C[(size_t)m0 * Dc + n0]) = make_float2(v0, v1);
                *reinterpret_cast<float2*>(&C[(size_t)(m0 + 8) * Dc + n0]) = make_float2(v2, v3);
            }
        }
    }
}

// ======= flash attention v7: uniform no-max fast path for ALL qtiles.
//         qtile 7 runs kt0=14; row 1023 (all-masked, l=0 -> NaN) is fixed by
//         fix1023 afterwards. Single barrier per k-tile.
#define FA3_P_WORDS (128*68)
#define FA3_SMEM (65536 + FA3_P_WORDS*4)   // 100352

__global__ void __launch_bounds__(256, 2)
flash_attn7(const float* __restrict__ Qg, const float* __restrict__ Kg,
            const float* __restrict__ Vt, const float* __restrict__ maskg,
            float* __restrict__ Og) {
    extern __shared__ uint32_t sm[];
    uint32_t* sp = sm + 16384;
    const uint32_t qkvb = smem_u32(sm);

    const int tid = threadIdx.x;
    const int wid = tid >> 5;
    const int lane = tid & 31;
    const int g = lane >> 2;
    const int tg = lane & 3;
    const int arowoff = ((lane >> 3) & 1) * 8 + (lane & 7);
    const int acbit   = (lane >> 4) & 1;
    const int browoff = ((lane >> 4) & 1) * 8 + (lane & 7);
    const int bcbit   = (lane >> 3) & 1;

    const int qtile = blockIdx.x;                 // heavy qtile 0 first
    const int bh = blockIdx.y;
    const int b = bh >> 4, h = bh & 15;
    const int q0 = qtile * 128;
    const size_t hb = (size_t)b * Tc * Dc + h * DHc;
    const float* vt_h = Vt + (size_t)bh * DHc * Tc;
    const int kt0 = (qtile < 7) ? 2 * qtile : 14;

    #pragma unroll
    for (int i = 0; i < 8; i++) {
        int ca = tid + i * 256;
        int row = ca >> 4, c = ca & 15;
        cp16(qkvb + sw256(row, c), Qg + hb + (size_t)(q0 + row) * Dc + c * 4);
    }
    cp_commit(); cp_wait<0>();
    __syncthreads();

    const int ra = wid * 16 + g;
    const int qa = q0 + ra, qb = qa + 8;

    uint32_t qf[8][4];
    {
        int row = wid * 16 + arowoff;
        #pragma unroll
        for (int s = 0; s < 8; s++) {
            uint32_t ad = qkvb + sw256(row, 2 * s + acbit);
            ldsm_x4(qf[s][0], qf[s][1], qf[s][2], qf[s][3], ad);
        }
    }
    __syncthreads();

    auto issue_kv = [&](int kt, int bufb) {
        uint32_t kbb = qkvb + bufb * 32768;
        uint32_t vbb = kbb + 16384;
        #pragma unroll
        for (int i = 0; i < 4; i++) {
            int ca = tid + i * 256;
            int row = ca >> 4, c = ca & 15;
            cp16(kbb + sw256(row, c), Kg + hb + (size_t)(kt * 64 + row) * Dc + c * 4);
            cp16(vbb + sw256(row, c), vt_h + (size_t)row * Tc + kt * 64 + c * 4);
        }
    };

    float l_a = 0.f, l_b = 0.f;
    float oacc[8][4];
    #pragma unroll
    for (int j = 0; j < 8; j++)
        #pragma unroll
        for (int r = 0; r < 4; r++) oacc[j][r] = 0.f;

    issue_kv(kt0, 0); cp_commit();
    int buf = 0;
    for (int kt = kt0; kt < 16; kt++) {
        cp_wait<0>();
        __syncthreads();
        if (kt + 1 < 16) { issue_kv(kt + 1, buf ^ 1); cp_commit(); }
        const uint32_t kb_s = qkvb + buf * 32768;
        const uint32_t vb_s = kb_s + 16384;

        // ---- S = Q K^T (Q pre-scaled by 0.125) ----
        float sacc[8][4];
        #pragma unroll
        for (int j = 0; j < 8; j++)
            #pragma unroll
            for (int r = 0; r < 4; r++) sacc[j][r] = 0.f;
        #pragma unroll
        for (int ks = 0; ks < 8; ks++) {
            uint32_t bfr[8][2];
            #pragma unroll
            for (int jp = 0; jp < 4; jp++) {
                int row = jp * 16 + browoff;
                uint32_t bd = kb_s + sw256(row, 2 * ks + bcbit);
                ldsm_x4(bfr[2 * jp][0], bfr[2 * jp][1],
                        bfr[2 * jp + 1][0], bfr[2 * jp + 1][1], bd);
            }
            #pragma unroll
            for (int j = 0; j < 8; j++)
                mma_tf32(sacc[j][0], sacc[j][1], sacc[j][2], sacc[j][3],
                         qf[ks][0], qf[ks][1], qf[ks][2], qf[ks][3],
                         bfr[j][0], bfr[j][1]);
        }

        // ---- causal mask on diagonal tiles ----
        if (kt < kt0 + 2) {
            #pragma unroll
            for (int j = 0; j < 8; j++) {
                #pragma unroll
                for (int r = 0; r < 4; r++) {
                    int col = 8 * j + 2 * tg + (r & 1);
                    int kg = kt * 64 + col;
                    int qrow = (r < 2) ? qa : qb;
                    if (kg <= qrow) sacc[j][r] -= 10000.f;
                }
            }
        }

        // ---- no-max softmax (scores bounded; masked entries underflow to 0)
        float rs_a = 0.f, rs_b = 0.f;
        #pragma unroll
        for (int j = 0; j < 8; j++) {
            float p0 = __expf(sacc[j][0]);
            float p1 = __expf(sacc[j][1]);
            float p2 = __expf(sacc[j][2]);
            float p3 = __expf(sacc[j][3]);
            sacc[j][0] = p0; sacc[j][1] = p1;
            sacc[j][2] = p2; sacc[j][3] = p3;
            rs_a += p0 + p1;
            rs_b += p2 + p3;
        }
        rs_a += __shfl_xor_sync(0xffffffff, rs_a, 1);
        rs_a += __shfl_xor_sync(0xffffffff, rs_a, 2);
        rs_b += __shfl_xor_sync(0xffffffff, rs_b, 1);
        rs_b += __shfl_xor_sync(0xffffffff, rs_b, 2);
        l_a += rs_a;
        l_b += rs_b;

        // ---- write P (tf32) to per-warp rows of sp ----
        #pragma unroll
        for (int j = 0; j < 8; j++) {
            uint2 pa = make_uint2(f2tf32(sacc[j][0]), f2tf32(sacc[j][1]));
            uint2 pb = make_uint2(f2tf32(sacc[j][2]), f2tf32(sacc[j][3]));
            *reinterpret_cast<uint2*>(&sp[ra * 68 + 8 * j + 2 * tg]) = pa;
            *reinterpret_cast<uint2*>(&sp[(ra + 8) * 68 + 8 * j + 2 * tg]) = pb;
        }
        __syncwarp();

        // ---- O += P V (V^T fragments via ldmatrix) ----
        #pragma unroll
        for (int s = 0; s < 8; s++) {
            uint32_t a0 = sp[ra * 68 + 8 * s + tg];
            uint32_t a1 = sp[(ra + 8) * 68 + 8 * s + tg];
            uint32_t a2 = sp[ra * 68 + 8 * s + tg + 4];
            uint32_t a3 = sp[(ra + 8) * 68 + 8 * s + tg + 4];
            uint32_t bfr[8][2];
            #pragma unroll
            for (int jp = 0; jp < 4; jp++) {
                int row = jp * 16 + browoff;
                uint32_t bd = vb_s + sw256(row, 2 * s + bcbit);
                ldsm_x4(bfr[2 * jp][0], bfr[2 * jp][1],
                        bfr[2 * jp + 1][0], bfr[2 * jp + 1][1], bd);
            }
            #pragma unroll
            for (int j = 0; j < 8; j++)
                mma_tf32(oacc[j][0], oacc[j][1], oacc[j][2], oacc[j][3],
                         a0, a1, a2, a3, bfr[j][0], bfr[j][1]);
        }
        buf ^= 1;
    }

    float sc_a = maskg[b * Tc + qa] / l_a;
    float sc_b = maskg[b * Tc + qb] / l_b;
    #pragma unroll
    for (int j = 0; j < 8; j++) {
        int col = h * DHc + 8 * j + 2 * tg;
        *reinterpret_cast<float2*>(&Og[(size_t)(b * Tc + qa) * Dc + col]) =
            make_float2(oacc[j][0] * sc_a, oacc[j][1] * sc_a);
        *reinterpret_cast<float2*>(&Og[(size_t)(b * Tc + qb) * Dc + col]) =
            make_float2(oacc[j][2] * sc_b, oacc[j][3] * sc_b);
    }
}

// ======= fix row 1023: out = softmax(s/8 - 10000) @ V  (shift applied in
//         fp32 to reproduce the reference's quantization), x mask ==========
__global__ __launch_bounds__(256)
void fix1023(const float* __restrict__ Qg, const float* __restrict__ Kg,
             const float* __restrict__ Vt, const float* __restrict__ maskg,
             float* __restrict__ Og) {
    const int bh = blockIdx.x, b = bh >> 4, h = bh & 15;
    const int tid = threadIdx.x;
    __shared__ float4 qv[16];
    __shared__ float pp[1024];
    __shared__ float red[8];
    __shared__ float outd[64];
    __shared__ float stot;
    const size_t hb = (size_t)b * Tc * Dc + h * DHc;
    if (tid < 16)
        qv[tid] = *reinterpret_cast<const float4*>(
            &Qg[hb + (size_t)1023 * Dc + tid * 4]);
    __syncthreads();
    float s[4]; float mx = -INFINITY;
    #pragma unroll
    for (int i = 0; i < 4; i++) {
        int t = tid + i * 256;
        const float4* kr = reinterpret_cast<const float4*>(&Kg[hb + (size_t)t * Dc]);
        float acc = 0.f;
        #pragma unroll
        for (int j = 0; j < 16; j++) {
            float4 kv = kr[j], qq = qv[j];
            acc += kv.x * qq.x + kv.y * qq.y + kv.z * qq.z + kv.w * qq.w;
        }
        s[i] = acc - 10000.f;       // reproduce reference quantization
        mx = fmaxf(mx, s[i]);
    }
    #pragma unroll
    for (int off = 16; off > 0; off >>= 1)
        mx = fmaxf(mx, __shfl_xor_sync(0xffffffffu, mx, off));
    if ((tid & 31) == 0) red[tid >> 5] = mx;
    __syncthreads();
    mx = red[0];
    #pragma unroll
    for (int w = 1; w < 8; w++) mx = fmaxf(mx, red[w]);
    float sum = 0.f;
    #pragma unroll
    for (int i = 0; i < 4; i++) {
        int t = tid + i * 256;
        float p = expf(s[i] - mx);
        pp[t] = p;
        sum += p;
    }
    #pragma unroll
    for (int off = 16; off > 0; off >>= 1)
        sum += __shfl_xor_sync(0xffffffffu, sum, off);
    __syncthreads();                 // done reading red (max)
    if ((tid & 31) == 0) red[tid >> 5] = sum;
    if (tid < 64) outd[tid] = 0.f;
    __syncthreads();
    if (tid == 0) {
        float ss = 0.f;
        for (int w = 0; w < 8; w++) ss += red[w];
        stot = ss;
    }
    const int d = tid & 63, part = tid >> 6;
    const float* vrow = Vt + (size_t)bh * DHc * Tc + (size_t)d * Tc + part * 256;
    const float* pr = pp + part * 256;
    float acc = 0.f;
    for (int t = 0; t < 256; t++) acc += pr[t] * vrow[t];
    atomicAdd(&outd[d], acc);
    __syncthreads();
    if (tid < 64)
        Og[(size_t)(b * Tc + 1023) * Dc + h * DHc + tid] =
            outd[tid] / stot * maskg[b * Tc + 1023];
}

// ---------- warp-per-row LN: h = LN(a + c), fp32 + bf16 copy ----------
__global__ __launch_bounds__(256)
void add_ln_w(const float* __restrict__ A, const float* __restrict__ Cv,
              const float* __restrict__ sc, const float* __restrict__ bi,
              float* __restrict__ O, uint32_t* __restrict__ Ob) {
    const int wid = threadIdx.x >> 5, lane = threadIdx.x & 31;
    const int row = blockIdx.x * 8 + wid;
    const float4* a4 = reinterpret_cast<const float4*>(A) + (size_t)row * 256;
    const float4* c4 = reinterpret_cast<const float4*>(Cv) + (size_t)row * 256;
    float4 v[8];
    float sum = 0.f, sq = 0.f;
    #pragma unroll
    for (int i = 0; i < 8; i++) {
        float4 a = a4[lane + i * 32];
        float4 c = c4[lane + i * 32];
        v[i] = make_float4(a.x + c.x, a.y + c.y, a.z + c.z, a.w + c.w);
        sum += v[i].x + v[i].y + v[i].z + v[i].w;
        sq += v[i].x * v[i].x + v[i].y * v[i].y + v[i].z * v[i].z + v[i].w * v[i].w;
    }
    #pragma unroll
    for (int off = 16; off > 0; off >>= 1) {
        sum += __shfl_xor_sync(0xffffffff, sum, off);
        sq  += __shfl_xor_sync(0xffffffff, sq, off);
    }
    float mean = sum * (1.f / Dc);
    float var = sq * (1.f / Dc) - mean * mean;
    float rs = rsqrtf(var + 1e-5f);
    #pragma unroll
    for (int i = 0; i < 8; i++) {
        int f = lane + i * 32;
        float4 s4 = reinterpret_cast<const float4*>(sc)[f];
        float4 b4 = reinterpret_cast<const float4*>(bi)[f];
        float o0 = (v[i].x - mean) * rs * s4.x + b4.x;
        float o1 = (v[i].y - mean) * rs * s4.y + b4.y;
        float o2 = (v[i].z - mean) * rs * s4.z + b4.z;
        float o3 = (v[i].w - mean) * rs * s4.w + b4.w;
        size_t gi = (size_t)row * 256 + f;
        reinterpret_cast<float4*>(O)[gi] = make_float4(o0, o1, o2, o3);
        Ob[gi * 2]     = pack_bf16x2(o0, o1);
        Ob[gi * 2 + 1] = pack_bf16x2(o2, o3);
    }
}

// ---------- warp-per-row: out = LN3(LN2(h1 + f2)) ----------
__global__ __launch_bounds__(256)
void ln2_ln3_w(const float* __restrict__ H1, const float* __restrict__ F2,
               const float* __restrict__ s2, const float* __restrict__ b2,
               const float* __restrict__ s3, const float* __restrict__ b3,
               float* __restrict__ O) {
    const int wid = threadIdx.x >> 5, lane = threadIdx.x & 31;
    const int row = blockIdx.x * 8 + wid;
    const float4* a4 = reinterpret_cast<const float4*>(H1) + (size_t)row * 256;
    const float4* c4 = reinterpret_cast<const float4*>(F2) + (size_t)row * 256;
    float4 v[8];
    float sum = 0.f, sq = 0.f;
    #pragma unroll
    for (int i = 0; i < 8; i++) {
        float4 a = a4[lane + i * 32];
        float4 c = c4[lane + i * 32];
        v[i] = make_float4(a.x + c.x, a.y + c.y, a.z + c.z, a.w + c.w);
        sum += v[i].x + v[i].y + v[i].z + v[i].w;
        sq += v[i].x * v[i].x + v[i].y * v[i].y + v[i].z * v[i].z + v[i].w * v[i].w;
    }
    #pragma unroll
    for (int off = 16; off > 0; off >>= 1) {
        sum += __shfl_xor_sync(0xffffffff, sum, off);
        sq  += __shfl_xor_sync(0xffffffff, sq, off);
    }
    float mean = sum * (1.f / Dc);
    float var = sq * (1.f / Dc) - mean * mean;
    float rs = rsqrtf(var + 1e-5f);
    sum = 0.f; sq = 0.f;
    #pragma unroll
    for (int i = 0; i < 8; i++) {
        int f = lane + i * 32;
        float4 s4 = reinterpret_cast<const float4*>(s2)[f];
        float4 b4 = reinterpret_cast<const float4*>(b2)[f];
        v[i].x = (v[i].x - mean) * rs * s4.x + b4.x;
        v[i].y = (v[i].y - mean) * rs * s4.y + b4.y;
        v[i].z = (v[i].z - mean) * rs * s4.z + b4.z;
        v[i].w = (v[i].w - mean) * rs * s4.w + b4.w;
        sum += v[i].x + v[i].y + v[i].z + v[i].w;
        sq += v[i].x * v[i].x + v[i].y * v[i].y + v[i].z * v[i].z + v[i].w * v[i].w;
    }
    #pragma unroll
    for (int off = 16; off > 0; off >>= 1) {
        sum += __shfl_xor_sync(0xffffffff, sum, off);
        sq  += __shfl_xor_sync(0xffffffff, sq, off);
    }
    float mean2 = sum * (1.f / Dc);
    float var2 = sq * (1.f / Dc) - mean2 * mean2;
    float rs2 = rsqrtf(var2 + 1e-5f);
    #pragma unroll
    for (int i = 0; i < 8; i++) {
        int f = lane + i * 32;
        float4 s4 = reinterpret_cast<const float4*>(s3)[f];
        float4 b4 = reinterpret_cast<const float4*>(b3)[f];
        float o0 = (v[i].x - mean2) * rs2 * s4.x + b4.x;
        float o1 = (v[i].y - mean2) * rs2 * s4.y + b4.y;
        float o2 = (v[i].z - mean2) * rs2 * s4.z + b4.z;
        float o3 = (v[i].w - mean2) * rs2 * s4.w + b4.w;
        reinterpret_cast<float4*>(O)[(size_t)row * 256 + f] = make_float4(o0, o1, o2, o3);
    }
}

// ---------------- launch ----------------
extern "C" void kernel_launch(void* const* d_in, const int* in_sizes, int n_in,
                              void* d_out, int out_size) {
    const float* x     = (const float*)d_in[0];
    const float* mask  = (const float*)d_in[1];
    const float* wq    = (const float*)d_in[2];
    const float* wk    = (const float*)d_in[3];
    const float* wv    = (const float*)d_in[4];
    const float* w1    = (const float*)d_in[5];
    const float* b1    = (const float*)d_in[6];
    const float* w2    = (const float*)d_in[7];
    const float* b2    = (const float*)d_in[8];
    const float* ln1s  = (const float*)d_in[9];
    const float* ln1b  = (const float*)d_in[10];
    const float* ln2s  = (const float*)d_in[11];
    const float* ln2b  = (const float*)d_in[12];
    const float* ln3s  = (const float*)d_in[13];
    const float* ln3b  = (const float*)d_in[14];
    float* out = (float*)d_out;

    float *q, *k, *vt, *att, *h1, *f2;
    uint32_t *xb, *wb, *h1b, *f1b;
    cudaGetSymbolAddress((void**)&q,   g_q);
    cudaGetSymbolAddress((void**)&k,   g_k);
    cudaGetSymbolAddress((void**)&vt,  g_vt);
    cudaGetSymbolAddress((void**)&att, g_att);
    cudaGetSymbolAddress((void**)&h1,  g_h1);
    cudaGetSymbolAddress((void**)&f2,  g_f2);
    cudaGetSymbolAddress((void**)&xb,  g_xb);
    cudaGetSymbolAddress((void**)&wb,  g_wb);
    cudaGetSymbolAddress((void**)&h1b, g_h1b);
    cudaGetSymbolAddress((void**)&f1b, g_f1b);

    cudaFuncSetAttribute(gemm_bf<false,false,true,true,false>,
                         cudaFuncAttributeMaxDynamicSharedMemorySize, GEMM2_SMEM);
    cudaFuncSetAttribute(gemm_bf<true,true,false,false,true>,
                         cudaFuncAttributeMaxDynamicSharedMemorySize, GEMM2_SMEM);
    cudaFuncSetAttribute(gemm_bf<false,true,false,false,false>,
                         cudaFuncAttributeMaxDynamicSharedMemorySize, GEMM2_SMEM);
    cudaFuncSetAttribute(flash_attn7,
                         cudaFuncAttributeMaxDynamicSharedMemorySize, FA3_SMEM);

    prep<<<9216, 256>>>(x, wq, wk, wv, w1, w2, xb, (__nv_bfloat16*)wb);

    const __nv_bfloat16* xbb = (const __nv_bfloat16*)xb;
    const __nv_bfloat16* wqb = (const __nv_bfloat16*)wb;
    const __nv_bfloat16* wkb = wqb + (size_t)1 * Dc * Dc;
    const __nv_bfloat16* wvb = wqb + (size_t)2 * Dc * Dc;
    const __nv_bfloat16* w1b = wqb + (size_t)3 * Dc * Dc;
    const __nv_bfloat16* w2b = wqb + (size_t)4 * Dc * Dc;

    gemm_bf<false,false,true,true,false><<<dim3(8, 32, 3), 256, GEMM2_SMEM>>>(
        xbb, wqb, wkb, wvb, nullptr, q, k, vt);

    flash_attn7<<<dim3(8, BHc), 256, FA3_SMEM>>>(q, k, vt, mask, att);
    fix1023<<<BHc, 256>>>(q, k, vt, mask, att);

    add_ln_w<<<Mrows / 8, 256>>>(x, att, ln1s, ln1b, h1, h1b);

    gemm_bf<true,true,false,false,true><<<dim3(8, 32, 1), 256, GEMM2_SMEM>>>(
        (const __nv_bfloat16*)h1b, w1b, w1b, w1b, b1,
        (float*)f1b, (float*)f1b, (float*)f1b);
    gemm_bf<false,true,false,false,false><<<dim3(8, 32, 1), 256, GEMM2_SMEM>>>(
        (const __nv_bfloat16*)f1b, w2b, w2b, w2b, b2, f2, f2, f2);

    ln2_ln3_w<<<Mrows / 8, 256>>>(h1, f2, ln2s, ln2b, ln3s, ln3b, out);
}

// round 15
// speedup vs baseline: 1.1032x; 1.1032x over previous
#include <cuda_runtime.h>
#include <cuda_bf16.h>
#include <math.h>
#include <stdint.h>

#define Bc 4
#define Tc 1024
#define Dc 1024
#define Hc 16
#define DHc 64
#define Mrows (Bc*Tc)          // 4096
#define BHc (Bc*Hc)            // 64

// ---------------- static scratch (no allocations allowed) ----------------
__device__ float g_q[Mrows*Dc];
__device__ float g_k[Mrows*Dc];
__device__ float g_vt[BHc*DHc*Tc];     // V transposed per (b,h): [d][T] (tf32 bits)
__device__ float g_att[Mrows*Dc];
__device__ float g_h1[Mrows*Dc];
__device__ float g_f2[Mrows*Dc];
__device__ uint32_t g_xb[Mrows*Dc/2];  // x as bf16 pairs
__device__ uint32_t g_wb[5*Dc*Dc/2];   // transposed weights as bf16
__device__ uint32_t g_h1b[Mrows*Dc/2];
__device__ uint32_t g_f1b[Mrows*Dc/2];

__device__ __forceinline__ uint32_t f2tf32(float f) {
    uint32_t r;
    asm("cvt.rna.tf32.f32 %0, %1;" : "=r"(r) : "f"(f));
    return r;
}
__device__ __forceinline__ uint32_t pack_bf16x2(float lo, float hi) {
    uint32_t r;
    asm("cvt.rn.bf16x2.f32 %0, %1, %2;" : "=r"(r) : "f"(hi), "f"(lo));
    return r;
}
__device__ __forceinline__ uint32_t smem_u32(const void* p) {
    uint32_t a;
    asm("{ .reg .u64 t; cvta.to.shared.u64 t, %1; cvt.u32.u64 %0, t; }" : "=r"(a) : "l"(p));
    return a;
}
__device__ __forceinline__ void mma_tf32(float& d0, float& d1, float& d2, float& d3,
                                         uint32_t a0, uint32_t a1, uint32_t a2, uint32_t a3,
                                         uint32_t b0, uint32_t b1) {
    asm volatile(
        "mma.sync.aligned.m16n8k8.row.col.f32.tf32.tf32.f32 "
        "{%0,%1,%2,%3},{%4,%5,%6,%7},{%8,%9},{%0,%1,%2,%3};"
        : "+f"(d0), "+f"(d1), "+f"(d2), "+f"(d3)
        : "r"(a0), "r"(a1), "r"(a2), "r"(a3), "r"(b0), "r"(b1));
}
__device__ __forceinline__ void mma_bf16(float& d0, float& d1, float& d2, float& d3,
                                         uint32_t a0, uint32_t a1, uint32_t a2, uint32_t a3,
                                         uint32_t b0, uint32_t b1) {
    asm volatile(
        "mma.sync.aligned.m16n8k16.row.col.f32.bf16.bf16.f32 "
        "{%0,%1,%2,%3},{%4,%5,%6,%7},{%8,%9},{%0,%1,%2,%3};"
        : "+f"(d0), "+f"(d1), "+f"(d2), "+f"(d3)
        : "r"(a0), "r"(a1), "r"(a2), "r"(a3), "r"(b0), "r"(b1));
}
__device__ __forceinline__ void ldsm_x4(uint32_t& r0, uint32_t& r1, uint32_t& r2,
                                        uint32_t& r3, uint32_t addr) {
    asm volatile("ldmatrix.sync.aligned.m8n8.x4.shared.b16 {%0,%1,%2,%3}, [%4];"
                 : "=r"(r0), "=r"(r1), "=r"(r2), "=r"(r3) : "r"(addr));
}
__device__ __forceinline__ void cp16(uint32_t dst, const void* src) {
    asm volatile("cp.async.cg.shared.global [%0], [%1], 16;" :: "r"(dst), "l"(src));
}
__device__ __forceinline__ void cp_commit() {
    asm volatile("cp.async.commit_group;");
}
template<int N>
__device__ __forceinline__ void cp_wait() {
    asm volatile("cp.async.wait_group %0;" :: "n"(N));
}
__device__ __forceinline__ uint32_t sw256(int row, int c) {
    return ((uint32_t)row << 8) + (((((c & 7) ^ (row & 7)) | (c & 8)) << 4));
}

// ========== merged pre-pass: weights -> transposed bf16, x -> bf16 =========
__global__ __launch_bounds__(256)
void prep(const float* __restrict__ x,
          const float* __restrict__ wq, const float* __restrict__ wk,
          const float* __restrict__ wv, const float* __restrict__ w1,
          const float* __restrict__ w2,
          uint32_t* __restrict__ xb, __nv_bfloat16* __restrict__ wb) {
    __shared__ float t[32][33];
    const int bx = blockIdx.x;
    if (bx < 5120) {
        const int seg = bx >> 10;
        const int within = bx & 1023;
        const int nb = (within & 31) * 32;
        const int kb = (within >> 5) * 32;
        const float* src = seg == 0 ? wq : seg == 1 ? wk : seg == 2 ? wv
                          : seg == 3 ? w1 : w2;
        __nv_bfloat16* dst = wb + (size_t)seg * Dc * Dc;
        const int tx = threadIdx.x & 31;
        const int ty = threadIdx.x >> 5;
        #pragma unroll
        for (int i = 0; i < 4; i++) {
            int k = kb + ty + i * 8;
            t[ty + i * 8][tx] = src[(size_t)k * Dc + nb + tx];
        }
        __syncthreads();
        #pragma unroll
        for (int i = 0; i < 4; i++) {
            int n = nb + ty + i * 8;
            dst[(size_t)n * Dc + kb + tx] = __float2bfloat16_rn(t[tx][ty + i * 8]);
        }
    } else {
        int i = (bx - 5120) * 256 + threadIdx.x;
        float4 v = reinterpret_cast<const float4*>(x)[i];
        xb[2 * i]     = pack_bf16x2(v.x, v.y);
        xb[2 * i + 1] = pack_bf16x2(v.z, v.w);
    }
}

// ================== cp.async + ldmatrix bf16 warp-MMA GEMM =================
#define GS 3
#define STAGE_BYTES 32768
#define GEMM2_SMEM (GS*STAGE_BYTES)    // 98304
#define KT2 16                          // 1024/64

template<bool RELU, bool BIAS, bool ROUND, bool TRANSV, bool OBF>
__global__ void __launch_bounds__(256, 2)
gemm_bf(const __nv_bfloat16* __restrict__ A,
        const __nv_bfloat16* __restrict__ W0, const __nv_bfloat16* __restrict__ W1,
        const __nv_bfloat16* __restrict__ W2,
        const float* __restrict__ bias,
        float* __restrict__ C0, float* __restrict__ C1, float* __restrict__ C2) {
    extern __shared__ uint32_t sm[];
    const uint32_t sbase = smem_u32(sm);
    const int tid = threadIdx.x;
    const int wid = tid >> 5, lane = tid & 31;
    const int warp_m = wid >> 2, warp_n = wid & 3;
    const int g = lane >> 2, tg = lane & 3;
    const int bm = blockIdx.y * 128, bn = blockIdx.x * 128;
    const int z = blockIdx.z;
    const __nv_bfloat16* W = z == 0 ? W0 : z == 1 ? W1 : W2;
    float* C = z == 0 ? C0 : z == 1 ? C1 : C2;
    const float oscale = (TRANSV && z == 0) ? 0.125f : 1.0f;

    float acc[4][4][4];
    #pragma unroll
    for (int i = 0; i < 4; i++)
        #pragma unroll
        for (int j = 0; j < 4; j++)
            #pragma unroll
            for (int r = 0; r < 4; r++) acc[i][j][r] = 0.f;

    const int arowoff = ((lane >> 3) & 1) * 8 + (lane & 7);
    const int acbit   = (lane >> 4) & 1;
    const int browoff = ((lane >> 4) & 1) * 8 + (lane & 7);
    const int bcbit   = (lane >> 3) & 1;

    auto issue = [&](int kt, int st) {
        uint32_t abase = sbase + st * STAGE_BYTES;
        uint32_t bbase = abase + 16384;
        #pragma unroll
        for (int i = 0; i < 4; i++) {
            int ca = tid + i * 256;
            int row = ca >> 3, c4 = ca & 7;
            uint32_t doff = row * 128 + ((c4 ^ (row & 7)) << 4);
            cp16(abase + doff, A + (size_t)(bm + row) * Dc + kt * 64 + c4 * 8);
            cp16(bbase + doff, W + (size_t)(bn + row) * Dc + kt * 64 + c4 * 8);
        }
    };

    auto compute = [&](int st) {
        uint32_t abase = sbase + st * STAGE_BYTES;
        uint32_t bbase = abase + 16384;
        #pragma unroll
        for (int s = 0; s < 4; s++) {
            uint32_t af[4][4];
            #pragma unroll
            for (int i = 0; i < 4; i++) {
                int row = warp_m * 64 + i * 16 + arowoff;
                uint32_t ad = abase + row * 128 + (((2 * s + acbit) ^ (row & 7)) << 4);
                ldsm_x4(af[i][0], af[i][1], af[i][2], af[i][3], ad);
            }
            uint32_t bf[4][2];
            #pragma unroll
            for (int jp = 0; jp < 2; jp++) {
                int row = warp_n * 32 + jp * 16 + browoff;
                uint32_t bd = bbase + row * 128 + (((2 * s + bcbit) ^ (row & 7)) << 4);
                ldsm_x4(bf[2 * jp][0], bf[2 * jp][1],
                        bf[2 * jp + 1][0], bf[2 * jp + 1][1], bd);
            }
            #pragma unroll
            for (int i = 0; i < 4; i++)
                #pragma unroll
                for (int j = 0; j < 4; j++)
                    mma_bf16(acc[i][j][0], acc[i][j][1], acc[i][j][2], acc[i][j][3],
                             af[i][0], af[i][1], af[i][2], af[i][3],
                             bf[j][0], bf[j][1]);
        }
    };

    issue(0, 0); cp_commit();
    issue(1, 1); cp_commit();
    for (int kt = 0; kt < KT2; kt++) {
        cp_wait<1>();
        __syncthreads();
        int nk = kt + 2;
        if (nk < KT2) issue(nk, nk - (nk / 3) * 3);
        cp_commit();
        compute(kt - (kt / 3) * 3);
    }
    cp_wait<0>();

    if (TRANSV && z == 2) {
        __syncthreads();
        float* sf = reinterpret_cast<float*>(sm);   // [128 n][132 pad] floats
        #pragma unroll
        for (int i = 0; i < 4; i++) {
            int ml = warp_m * 64 + i * 16 + g;
            #pragma unroll
            for (int j = 0; j < 4; j++) {
                int nl = warp_n * 32 + j * 8 + tg * 2;
                float v0 = acc[i][j][0], v1 = acc[i][j][1];
                float v2 = acc[i][j][2], v3 = acc[i][j][3];
                if (ROUND) {
                    v0 = __uint_as_float(f2tf32(v0));
                    v1 = __uint_as_float(f2tf32(v1));
                    v2 = __uint_as_float(f2tf32(v2));
                    v3 = __uint_as_float(f2tf32(v3));
                }
                sf[nl * 132 + ml]           = v0;
                sf[(nl + 1) * 132 + ml]     = v1;
                sf[nl * 132 + ml + 8]       = v2;
                sf[(nl + 1) * 132 + ml + 8] = v3;
            }
        }
        __syncthreads();
        const int b_ = bm >> 10;
        const int t0 = bm & 1023;
        #pragma unroll
        for (int it = 0; it < 16; it++) {
            int idx = tid + it * 256;
            int nl = idx >> 5, m4 = (idx & 31) << 2;
            float4 vv = *reinterpret_cast<float4*>(&sf[nl * 132 + m4]);
            int h_ = (bn + nl) >> 6, dd = (bn + nl) & 63;
            float* dst = C + ((size_t)((b_ << 4) + h_) * 64 + dd) * 1024 + t0 + m4;
            *reinterpret_cast<float4*>(dst) = vv;
        }
        return;
    }

    #pragma unroll
    for (int i = 0; i < 4; i++) {
        int m0 = bm + warp_m * 64 + i * 16 + g;
        #pragma unroll
        for (int j = 0; j < 4; j++) {
            int n0 = bn + warp_n * 32 + j * 8 + tg * 2;
            float v0 = acc[i][j][0], v1 = acc[i][j][1];
            float v2 = acc[i][j][2], v3 = acc[i][j][3];
            if (BIAS) {
                float b0v = bias[n0], b1v = bias[n0 + 1];
                v0 += b0v; v1 += b1v; v2 += b0v; v3 += b1v;
            }
            if (RELU) {
                v0 = fmaxf(v0, 0.f); v1 = fmaxf(v1, 0.f);
                v2 = fmaxf(v2, 0.f); v3 = fmaxf(v3, 0.f);
            }
            if (TRANSV) { v0 *= oscale; v1 *= oscale; v2 *= oscale; v3 *= oscale; }
            if (ROUND) {
                v0 = __uint_as_float(f2tf32(v0));
                v1 = __uint_as_float(f2tf32(v1));
                v2 = __uint_as_float(f2tf32(v2));
                v3 = __uint_as_float(f2tf32(v3));
            }
            if (OBF) {
                uint32_t* Cb = reinterpret_cast<uint32_t*>(C);
                Cb[((size_t)m0 * Dc + n0) >> 1] = pack_bf16x2(v0, v1);
                Cb[((size_t)(m0 + 8) * Dc + n0) >> 1] = pack_bf16x2(v2, v3);
            } else {
                *reinterpret_cast<float2*>(&C[(size_t)m0 * Dc + n0]) = make_float2(v0, v1);
                *reinterpret_cast<float2*>(&C[(size_t)(m0 + 8) * Dc + n0]) = make_float2(v2, v3);
            }
        }
    }
}

// ======= flash attention v7: uniform no-max fast path for ALL qtiles.
//         qtile 7 runs kt0=14; row 1023 (all-masked, l=0 -> NaN) is fixed by
//         fix1023 afterwards. Single barrier per k-tile.
#define FA3_P_WORDS (128*68)
#define FA3_SMEM (65536 + FA3_P_WORDS*4)   // 100352

__global__ void __launch_bounds__(256, 2)
flash_attn7(const float* __restrict__ Qg, const float* __restrict__ Kg,
            const float* __restrict__ Vt, const float* __restrict__ maskg,
            float* __restrict__ Og) {
    extern __shared__ uint32_t sm[];
    uint32_t* sp = sm + 16384;
    const uint32_t qkvb = smem_u32(sm);

    const int tid = threadIdx.x;
    const int wid = tid >> 5;
    const int lane = tid & 31;
    const int g = lane >> 2;
    const int tg = lane & 3;
    const int arowoff = ((lane >> 3) & 1) * 8 + (lane & 7);
    const int acbit   = (lane >> 4) & 1;
    const int browoff = ((lane >> 4) & 1) * 8 + (lane & 7);
    const int bcbit   = (lane >> 3) & 1;

    const int qtile = blockIdx.x;
    const int bh = blockIdx.y;
    const int b = bh >> 4, h = bh & 15;
    const int q0 = qtile * 128;
    const size_t hb = (size_t)b * Tc * Dc + h * DHc;
    const float* vt_h = Vt + (size_t)bh * DHc * Tc;
    const int kt0 = (qtile < 7) ? 2 * qtile : 14;

    #pragma unroll
    for (int i = 0; i < 8; i++) {
        int ca = tid + i * 256;
        int row = ca >> 4, c = ca & 15;
        cp16(qkvb + sw256(row, c), Qg + hb + (size_t)(q0 + row) * Dc + c * 4);
    }
    cp_commit(); cp_wait<0>();
    __syncthreads();

    const int ra = wid * 16 + g;
    const int qa = q0 + ra, qb = qa + 8;

    uint32_t qf[8][4];
    {
        int row = wid * 16 + arowoff;
        #pragma unroll
        for (int s = 0; s < 8; s++) {
            uint32_t ad = qkvb + sw256(row, 2 * s + acbit);
            ldsm_x4(qf[s][0], qf[s][1], qf[s][2], qf[s][3], ad);
        }
    }
    __syncthreads();

    auto issue_kv = [&](int kt, int bufb) {
        uint32_t kbb = qkvb + bufb * 32768;
        uint32_t vbb = kbb + 16384;
        #pragma unroll
        for (int i = 0; i < 4; i++) {
            int ca = tid + i * 256;
            int row = ca >> 4, c = ca & 15;
            cp16(kbb + sw256(row, c), Kg + hb + (size_t)(kt * 64 + row) * Dc + c * 4);
            cp16(vbb + sw256(row, c), vt_h + (size_t)row * Tc + kt * 64 + c * 4);
        }
    };

    float l_a = 0.f, l_b = 0.f;
    float oacc[8][4];
    #pragma unroll
    for (int j = 0; j < 8; j++)
        #pragma unroll
        for (int r = 0; r < 4; r++) oacc[j][r] = 0.f;

    issue_kv(kt0, 0); cp_commit();
    int buf = 0;
    for (int kt = kt0; kt < 16; kt++) {
        cp_wait<0>();
        __syncthreads();
        if (kt + 1 < 16) { issue_kv(kt + 1, buf ^ 1); cp_commit(); }
        const uint32_t kb_s = qkvb + buf * 32768;
        const uint32_t vb_s = kb_s + 16384;

        float sacc[8][4];
        #pragma unroll
        for (int j = 0; j < 8; j++)
            #pragma unroll
            for (int r = 0; r < 4; r++) sacc[j][r] = 0.f;
        #pragma unroll
        for (int ks = 0; ks < 8; ks++) {
            uint32_t bfr[8][2];
            #pragma unroll
            for (int jp = 0; jp < 4; jp++) {
                int row = jp * 16 + browoff;
                uint32_t bd = kb_s + sw256(row, 2 * ks + bcbit);
                ldsm_x4(bfr[2 * jp][0], bfr[2 * jp][1],
                        bfr[2 * jp + 1][0], bfr[2 * jp + 1][1], bd);
            }
            #pragma unroll
            for (int j = 0; j < 8; j++)
                mma_tf32(sacc[j][0], sacc[j][1], sacc[j][2], sacc[j][3],
                         qf[ks][0], qf[ks][1], qf[ks][2], qf[ks][3],
                         bfr[j][0], bfr[j][1]);
        }

        if (kt < kt0 + 2) {
            #pragma unroll
            for (int j = 0; j < 8; j++) {
                #pragma unroll
                for (int r = 0; r < 4; r++) {
                    int col = 8 * j + 2 * tg + (r & 1);
                    int kg = kt * 64 + col;
                    int qrow = (r < 2) ? qa : qb;
                    if (kg <= qrow) sacc[j][r] -= 10000.f;
                }
            }
        }

        float rs_a = 0.f, rs_b = 0.f;
        #pragma unroll
        for (int j = 0; j < 8; j++) {
            float p0 = __expf(sacc[j][0]);
            float p1 = __expf(sacc[j][1]);
            float p2 = __expf(sacc[j][2]);
            float p3 = __expf(sacc[j][3]);
            sacc[j][0] = p0; sacc[j][1] = p1;
            sacc[j][2] = p2; sacc[j][3] = p3;
            rs_a += p0 + p1;
            rs_b += p2 + p3;
        }
        rs_a += __shfl_xor_sync(0xffffffff, rs_a, 1);
        rs_a += __shfl_xor_sync(0xffffffff, rs_a, 2);
        rs_b += __shfl_xor_sync(0xffffffff, rs_b, 1);
        rs_b += __shfl_xor_sync(0xffffffff, rs_b, 2);
        l_a += rs_a;
        l_b += rs_b;

        #pragma unroll
        for (int j = 0; j < 8; j++) {
            uint2 pa = make_uint2(f2tf32(sacc[j][0]), f2tf32(sacc[j][1]));
            uint2 pb = make_uint2(f2tf32(sacc[j][2]), f2tf32(sacc[j][3]));
            *reinterpret_cast<uint2*>(&sp[ra * 68 + 8 * j + 2 * tg]) = pa;
            *reinterpret_cast<uint2*>(&sp[(ra + 8) * 68 + 8 * j + 2 * tg]) = pb;
        }
        __syncwarp();

        #pragma unroll
        for (int s = 0; s < 8; s++) {
            uint32_t a0 = sp[ra * 68 + 8 * s + tg];
            uint32_t a1 = sp[(ra + 8) * 68 + 8 * s + tg];
            uint32_t a2 = sp[ra * 68 + 8 * s + tg + 4];
            uint32_t a3 = sp[(ra + 8) * 68 + 8 * s + tg + 4];
            uint32_t bfr[8][2];
            #pragma unroll
            for (int jp = 0; jp < 4; jp++) {
                int row = jp * 16 + browoff;
                uint32_t bd = vb_s + sw256(row, 2 * s + bcbit);
                ldsm_x4(bfr[2 * jp][0], bfr[2 * jp][1],
                        bfr[2 * jp + 1][0], bfr[2 * jp + 1][1], bd);
            }
            #pragma unroll
            for (int j = 0; j < 8; j++)
                mma_tf32(oacc[j][0], oacc[j][1], oacc[j][2], oacc[j][3],
                         a0, a1, a2, a3, bfr[j][0], bfr[j][1]);
        }
        buf ^= 1;
    }

    float sc_a = maskg[b * Tc + qa] / l_a;
    float sc_b = maskg[b * Tc + qb] / l_b;
    #pragma unroll
    for (int j = 0; j < 8; j++) {
        int col = h * DHc + 8 * j + 2 * tg;
        *reinterpret_cast<float2*>(&Og[(size_t)(b * Tc + qa) * Dc + col]) =
            make_float2(oacc[j][0] * sc_a, oacc[j][1] * sc_a);
        *reinterpret_cast<float2*>(&Og[(size_t)(b * Tc + qb) * Dc + col]) =
            make_float2(oacc[j][2] * sc_b, oacc[j][3] * sc_b);
    }
}

// ======= fix row 1023: out = softmax(s/8 - 10000) @ V, x mask.
//         V-accumulation restructured: warp-per-8d, lanes stride t
//         coalesced, shfl reduce (was: uncoalesced 256-deep serial chain).
__global__ __launch_bounds__(256)
void fix1023(const float* __restrict__ Qg, const float* __restrict__ Kg,
             const float* __restrict__ Vt, const float* __restrict__ maskg,
             float* __restrict__ Og) {
    const int bh = blockIdx.x, b = bh >> 4, h = bh & 15;
    const int tid = threadIdx.x;
    const int w = tid >> 5, lane = tid & 31;
    __shared__ float4 qv[16];
    __shared__ float pp[1024];
    __shared__ float red[8];
    __shared__ float stot;
    const size_t hb = (size_t)b * Tc * Dc + h * DHc;
    if (tid < 16)
        qv[tid] = *reinterpret_cast<const float4*>(
            &Qg[hb + (size_t)1023 * Dc + tid * 4]);
    __syncthreads();
    // ---- scores for all 1024 keys (4 per thread) ----
    float s[4]; float mx = -INFINITY;
    #pragma unroll
    for (int i = 0; i < 4; i++) {
        int t = tid + i * 256;
        const float4* kr = reinterpret_cast<const float4*>(&Kg[hb + (size_t)t * Dc]);
        float acc = 0.f;
        #pragma unroll
        for (int j = 0; j < 16; j++) {
            float4 kv = kr[j], qq = qv[j];
            acc += kv.x * qq.x + kv.y * qq.y + kv.z * qq.z + kv.w * qq.w;
        }
        s[i] = acc - 10000.f;       // reproduce reference quantization
        mx = fmaxf(mx, s[i]);
    }
    #pragma unroll
    for (int off = 16; off > 0; off >>= 1)
        mx = fmaxf(mx, __shfl_xor_sync(0xffffffffu, mx, off));
    if (lane == 0) red[w] = mx;
    __syncthreads();
    mx = red[0];
    #pragma unroll
    for (int ww = 1; ww < 8; ww++) mx = fmaxf(mx, red[ww]);
    float sum = 0.f;
    #pragma unroll
    for (int i = 0; i < 4; i++) {
        int t = tid + i * 256;
        float p = expf(s[i] - mx);
        pp[t] = p;
        sum += p;
    }
    #pragma unroll
    for (int off = 16; off > 0; off >>= 1)
        sum += __shfl_xor_sync(0xffffffffu, sum, off);
    __syncthreads();                 // all reads of red (max) done
    if (lane == 0) red[w] = sum;
    __syncthreads();
    if (tid == 0) {
        float ss = 0.f;
        for (int ww = 0; ww < 8; ww++) ss += red[ww];
        stot = ss;
    }
    __syncthreads();
    // ---- O[d] = sum_t pp[t] * Vt[d][t]: warp w owns d in [8w, 8w+8) ----
    const float* vbase = Vt + (size_t)bh * DHc * Tc;
    float accs[8];
    #pragma unroll
    for (int dd = 0; dd < 8; dd++) {
        const float* vr = vbase + (size_t)(w * 8 + dd) * Tc;
        float acc = 0.f;
        #pragma unroll
        for (int i = 0; i < 32; i++)
            acc += pp[lane + i * 32] * vr[lane + i * 32];
        accs[dd] = acc;
    }
    const float scale = maskg[b * Tc + 1023] / stot;
    #pragma unroll
    for (int dd = 0; dd < 8; dd++) {
        float a = accs[dd];
        #pragma unroll
        for (int off = 16; off > 0; off >>= 1)
            a += __shfl_xor_sync(0xffffffffu, a, off);
        if (lane == 0)
            Og[(size_t)(b * Tc + 1023) * Dc + h * DHc + w * 8 + dd] = a * scale;
    }
}

// ---------- warp-per-row LN: h = LN(a + c), fp32 + bf16 copy ----------
__global__ __launch_bounds__(256)
void add_ln_w(const float* __restrict__ A, const float* __restrict__ Cv,
              const float* __restrict__ sc, const float* __restrict__ bi,
              float* __restrict__ O, uint32_t* __restrict__ Ob) {
    const int wid = threadIdx.x >> 5, lane = threadIdx.x & 31;
    const int row = blockIdx.x * 8 + wid;
    const float4* a4 = reinterpret_cast<const float4*>(A) + (size_t)row * 256;
    const float4* c4 = reinterpret_cast<const float4*>(Cv) + (size_t)row * 256;
    float4 v[8];
    float sum = 0.f, sq = 0.f;
    #pragma unroll
    for (int i = 0; i < 8; i++) {
        float4 a = a4[lane + i * 32];
        float4 c = c4[lane + i * 32];
        v[i] = make_float4(a.x + c.x, a.y + c.y, a.z + c.z, a.w + c.w);
        sum += v[i].x + v[i].y + v[i].z + v[i].w;
        sq += v[i].x * v[i].x + v[i].y * v[i].y + v[i].z * v[i].z + v[i].w * v[i].w;
    }
    #pragma unroll
    for (int off = 16; off > 0; off >>= 1) {
        sum += __shfl_xor_sync(0xffffffff, sum, off);
        sq  += __shfl_xor_sync(0xffffffff, sq, off);
    }
    float mean = sum * (1.f / Dc);
    float var = sq * (1.f / Dc) - mean * mean;
    float rs = rsqrtf(var + 1e-5f);
    #pragma unroll
    for (int i = 0; i < 8; i++) {
        int f = lane + i * 32;
        float4 s4 = reinterpret_cast<const float4*>(sc)[f];
        float4 b4 = reinterpret_cast<const float4*>(bi)[f];
        float o0 = (v[i].x - mean) * rs * s4.x + b4.x;
        float o1 = (v[i].y - mean) * rs * s4.y + b4.y;
        float o2 = (v[i].z - mean) * rs * s4.z + b4.z;
        float o3 = (v[i].w - mean) * rs * s4.w + b4.w;
        size_t gi = (size_t)row * 256 + f;
        reinterpret_cast<float4*>(O)[gi] = make_float4(o0, o1, o2, o3);
        Ob[gi * 2]     = pack_bf16x2(o0, o1);
        Ob[gi * 2 + 1] = pack_bf16x2(o2, o3);
    }
}

// ---------- warp-per-row: out = LN3(LN2(h1 + f2)) ----------
__global__ __launch_bounds__(256)
void ln2_ln3_w(const float* __restrict__ H1, const float* __restrict__ F2,
               const float* __restrict__ s2, const float* __restrict__ b2,
               const float* __restrict__ s3, const float* __restrict__ b3,
               float* __restrict__ O) {
    const int wid = threadIdx.x >> 5, lane = threadIdx.x & 31;
    const int row = blockIdx.x * 8 + wid;
    const float4* a4 = reinterpret_cast<const float4*>(H1) + (size_t)row * 256;
    const float4* c4 = reinterpret_cast<const float4*>(F2) + (size_t)row * 256;
    float4 v[8];
    float sum = 0.f, sq = 0.f;
    #pragma unroll
    for (int i = 0; i < 8; i++) {
        float4 a = a4[lane + i * 32];
        float4 c = c4[lane + i * 32];
        v[i] = make_float4(a.x + c.x, a.y + c.y, a.z + c.z, a.w + c.w);
        sum += v[i].x + v[i].y + v[i].z + v[i].w;
        sq += v[i].x * v[i].x + v[i].y * v[i].y + v[i].z * v[i].z + v[i].w * v[i].w;
    }
    #pragma unroll
    for (int off = 16; off > 0; off >>= 1) {
        sum += __shfl_xor_sync(0xffffffff, sum, off);
        sq  += __shfl_xor_sync(0xffffffff, sq, off);
    }
    float mean = sum * (1.f / Dc);
    float var = sq * (1.f / Dc) - mean * mean;
    float rs = rsqrtf(var + 1e-5f);
    sum = 0.f; sq = 0.f;
    #pragma unroll
    for (int i = 0; i < 8; i++) {
        int f = lane + i * 32;
        float4 s4 = reinterpret_cast<const float4*>(s2)[f];
        float4 b4 = reinterpret_cast<const float4*>(b2)[f];
        v[i].x = (v[i].x - mean) * rs * s4.x + b4.x;
        v[i].y = (v[i].y - mean) * rs * s4.y + b4.y;
        v[i].z = (v[i].z - mean) * rs * s4.z + b4.z;
        v[i].w = (v[i].w - mean) * rs * s4.w + b4.w;
        sum += v[i].x + v[i].y + v[i].z + v[i].w;
        sq += v[i].x * v[i].x + v[i].y * v[i].y + v[i].z * v[i].z + v[i].w * v[i].w;
    }
    #pragma unroll
    for (int off = 16; off > 0; off >>= 1) {
        sum += __shfl_xor_sync(0xffffffff, sum, off);
        sq  += __shfl_xor_sync(0xffffffff, sq, off);
    }
    float mean2 = sum * (1.f / Dc);
    float var2 = sq * (1.f / Dc) - mean2 * mean2;
    float rs2 = rsqrtf(var2 + 1e-5f);
    #pragma unroll
    for (int i = 0; i < 8; i++) {
        int f = lane + i * 32;
        float4 s4 = reinterpret_cast<const float4*>(s3)[f];
        float4 b4 = reinterpret_cast<const float4*>(b3)[f];
        float o0 = (v[i].x - mean2) * rs2 * s4.x + b4.x;
        float o1 = (v[i].y - mean2) * rs2 * s4.y + b4.y;
        float o2 = (v[i].z - mean2) * rs2 * s4.z + b4.z;
        float o3 = (v[i].w - mean2) * rs2 * s4.w + b4.w;
        reinterpret_cast<float4*>(O)[(size_t)row * 256 + f] = make_float4(o0, o1, o2, o3);
    }
}

// ---------------- launch ----------------
extern "C" void kernel_launch(void* const* d_in, const int* in_sizes, int n_in,
                              void* d_out, int out_size) {
    const float* x     = (const float*)d_in[0];
    const float* mask  = (const float*)d_in[1];
    const float* wq    = (const float*)d_in[2];
    const float* wk    = (const float*)d_in[3];
    const float* wv    = (const float*)d_in[4];
    const float* w1    = (const float*)d_in[5];
    const float* b1    = (const float*)d_in[6];
    const float* w2    = (const float*)d_in[7];
    const float* b2    = (const float*)d_in[8];
    const float* ln1s  = (const float*)d_in[9];
    const float* ln1b  = (const float*)d_in[10];
    const float* ln2s  = (const float*)d_in[11];
    const float* ln2b  = (const float*)d_in[12];
    const float* ln3s  = (const float*)d_in[13];
    const float* ln3b  = (const float*)d_in[14];
    float* out = (float*)d_out;

    float *q, *k, *vt, *att, *h1, *f2;
    uint32_t *xb, *wb, *h1b, *f1b;
    cudaGetSymbolAddress((void**)&q,   g_q);
    cudaGetSymbolAddress((void**)&k,   g_k);
    cudaGetSymbolAddress((void**)&vt,  g_vt);
    cudaGetSymbolAddress((void**)&att, g_att);
    cudaGetSymbolAddress((void**)&h1,  g_h1);
    cudaGetSymbolAddress((void**)&f2,  g_f2);
    cudaGetSymbolAddress((void**)&xb,  g_xb);
    cudaGetSymbolAddress((void**)&wb,  g_wb);
    cudaGetSymbolAddress((void**)&h1b, g_h1b);
    cudaGetSymbolAddress((void**)&f1b, g_f1b);

    cudaFuncSetAttribute(gemm_bf<false,false,true,true,false>,
                         cudaFuncAttributeMaxDynamicSharedMemorySize, GEMM2_SMEM);
    cudaFuncSetAttribute(gemm_bf<true,true,false,false,true>,
                         cudaFuncAttributeMaxDynamicSharedMemorySize, GEMM2_SMEM);
    cudaFuncSetAttribute(gemm_bf<false,true,false,false,false>,
                         cudaFuncAttributeMaxDynamicSharedMemorySize, GEMM2_SMEM);
    cudaFuncSetAttribute(flash_attn7,
                         cudaFuncAttributeMaxDynamicSharedMemorySize, FA3_SMEM);

    prep<<<9216, 256>>>(x, wq, wk, wv, w1, w2, xb, (__nv_bfloat16*)wb);

    const __nv_bfloat16* xbb = (const __nv_bfloat16*)xb;
    const __nv_bfloat16* wqb = (const __nv_bfloat16*)wb;
    const __nv_bfloat16* wkb = wqb + (size_t)1 * Dc * Dc;
    const __nv_bfloat16* wvb = wqb + (size_t)2 * Dc * Dc;
    const __nv_bfloat16* w1b = wqb + (size_t)3 * Dc * Dc;
    const __nv_bfloat16* w2b = wqb + (size_t)4 * Dc * Dc;

    gemm_bf<false,false,true,true,false><<<dim3(8, 32, 3), 256, GEMM2_SMEM>>>(
        xbb, wqb, wkb, wvb, nullptr, q, k, vt);

    flash_attn7<<<dim3(8, BHc), 256, FA3_SMEM>>>(q, k, vt, mask, att);
    fix1023<<<BHc, 256>>>(q, k, vt, mask, att);

    add_ln_w<<<Mrows / 8, 256>>>(x, att, ln1s, ln1b, h1, h1b);

    gemm_bf<true,true,false,false,true><<<dim3(8, 32, 1), 256, GEMM2_SMEM>>>(
        (const __nv_bfloat16*)h1b, w1b, w1b, w1b, b1,
        (float*)f1b, (float*)f1b, (float*)f1b);
    gemm_bf<false,true,false,false,false><<<dim3(8, 32, 1), 256, GEMM2_SMEM>>>(
        (const __nv_bfloat16*)f1b, w2b, w2b, w2b, b2, f2, f2, f2);

    ln2_ln3_w<<<Mrows / 8, 256>>>(h1, f2, ln2s, ln2b, ln3s, ln3b, out);
}

// round 16
// speedup vs baseline: 1.1201x; 1.0154x over previous
#include <cuda_runtime.h>
#include <cuda_bf16.h>
#include <math.h>
#include <stdint.h>

#define Bc 4
#define Tc 1024
#define Dc 1024
#define Hc 16
#define DHc 64
#define Mrows (Bc*Tc)          // 4096
#define BHc (Bc*Hc)            // 64

// ---------------- static scratch (no allocations allowed) ----------------
__device__ float g_q[Mrows*Dc];
__device__ float g_k[Mrows*Dc];
__device__ float g_vt[BHc*DHc*Tc];     // V transposed per (b,h): [d][T] (tf32 bits)
__device__ float g_att[Mrows*Dc];
__device__ float g_h1[Mrows*Dc];
__device__ float g_f2[Mrows*Dc];
__device__ uint32_t g_xb[Mrows*Dc/2];  // x as bf16 pairs
__device__ uint32_t g_wb[5*Dc*Dc/2];   // transposed weights as bf16
__device__ uint32_t g_h1b[Mrows*Dc/2];
__device__ uint32_t g_f1b[Mrows*Dc/2];

__device__ __forceinline__ uint32_t f2tf32(float f) {
    uint32_t r;
    asm("cvt.rna.tf32.f32 %0, %1;" : "=r"(r) : "f"(f));
    return r;
}
__device__ __forceinline__ uint32_t pack_bf16x2(float lo, float hi) {
    uint32_t r;
    asm("cvt.rn.bf16x2.f32 %0, %1, %2;" : "=r"(r) : "f"(hi), "f"(lo));
    return r;
}
__device__ __forceinline__ uint32_t smem_u32(const void* p) {
    uint32_t a;
    asm("{ .reg .u64 t; cvta.to.shared.u64 t, %1; cvt.u32.u64 %0, t; }" : "=r"(a) : "l"(p));
    return a;
}
__device__ __forceinline__ void mma_tf32(float& d0, float& d1, float& d2, float& d3,
                                         uint32_t a0, uint32_t a1, uint32_t a2, uint32_t a3,
                                         uint32_t b0, uint32_t b1) {
    asm volatile(
        "mma.sync.aligned.m16n8k8.row.col.f32.tf32.tf32.f32 "
        "{%0,%1,%2,%3},{%4,%5,%6,%7},{%8,%9},{%0,%1,%2,%3};"
        : "+f"(d0), "+f"(d1), "+f"(d2), "+f"(d3)
        : "r"(a0), "r"(a1), "r"(a2), "r"(a3), "r"(b0), "r"(b1));
}
__device__ __forceinline__ void mma_bf16(float& d0, float& d1, float& d2, float& d3,
                                         uint32_t a0, uint32_t a1, uint32_t a2, uint32_t a3,
                                         uint32_t b0, uint32_t b1) {
    asm volatile(
        "mma.sync.aligned.m16n8k16.row.col.f32.bf16.bf16.f32 "
        "{%0,%1,%2,%3},{%4,%5,%6,%7},{%8,%9},{%0,%1,%2,%3};"
        : "+f"(d0), "+f"(d1), "+f"(d2), "+f"(d3)
        : "r"(a0), "r"(a1), "r"(a2), "r"(a3), "r"(b0), "r"(b1));
}
__device__ __forceinline__ void ldsm_x4(uint32_t& r0, uint32_t& r1, uint32_t& r2,
                                        uint32_t& r3, uint32_t addr) {
    asm volatile("ldmatrix.sync.aligned.m8n8.x4.shared.b16 {%0,%1,%2,%3}, [%4];"
                 : "=r"(r0), "=r"(r1), "=r"(r2), "=r"(r3) : "r"(addr));
}
__device__ __forceinline__ void cp16(uint32_t dst, const void* src) {
    asm volatile("cp.async.cg.shared.global [%0], [%1], 16;" :: "r"(dst), "l"(src));
}
__device__ __forceinline__ void cp_commit() {
    asm volatile("cp.async.commit_group;");
}
template<int N>
__device__ __forceinline__ void cp_wait() {
    asm volatile("cp.async.wait_group %0;" :: "n"(N));
}
__device__ __forceinline__ uint32_t sw256(int row, int c) {
    return ((uint32_t)row << 8) + (((((c & 7) ^ (row & 7)) | (c & 8)) << 4));
}

// ========== merged pre-pass: weights -> transposed bf16, x -> bf16 =========
__global__ __launch_bounds__(256)
void prep(const float* __restrict__ x,
          const float* __restrict__ wq, const float* __restrict__ wk,
          const float* __restrict__ wv, const float* __restrict__ w1,
          const float* __restrict__ w2,
          uint32_t* __restrict__ xb, __nv_bfloat16* __restrict__ wb) {
    __shared__ float t[32][33];
    const int bx = blockIdx.x;
    if (bx < 5120) {
        const int seg = bx >> 10;
        const int within = bx & 1023;
        const int nb = (within & 31) * 32;
        const int kb = (within >> 5) * 32;
        const float* src = seg == 0 ? wq : seg == 1 ? wk : seg == 2 ? wv
                          : seg == 3 ? w1 : w2;
        __nv_bfloat16* dst = wb + (size_t)seg * Dc * Dc;
        const int tx = threadIdx.x & 31;
        const int ty = threadIdx.x >> 5;
        #pragma unroll
        for (int i = 0; i < 4; i++) {
            int k = kb + ty + i * 8;
            t[ty + i * 8][tx] = src[(size_t)k * Dc + nb + tx];
        }
        __syncthreads();
        #pragma unroll
        for (int i = 0; i < 4; i++) {
            int n = nb + ty + i * 8;
            dst[(size_t)n * Dc + kb + tx] = __float2bfloat16_rn(t[tx][ty + i * 8]);
        }
    } else {
        int i = (bx - 5120) * 256 + threadIdx.x;
        float4 v = reinterpret_cast<const float4*>(x)[i];
        xb[2 * i]     = pack_bf16x2(v.x, v.y);
        xb[2 * i + 1] = pack_bf16x2(v.z, v.w);
    }
}

// ================== cp.async + ldmatrix bf16 warp-MMA GEMM =================
#define GS 3
#define STAGE_BYTES 32768
#define GEMM2_SMEM (GS*STAGE_BYTES)    // 98304
#define KT2 16                          // 1024/64

template<bool RELU, bool BIAS, bool ROUND, bool TRANSV, bool OBF>
__global__ void __launch_bounds__(256, 2)
gemm_bf(const __nv_bfloat16* __restrict__ A,
        const __nv_bfloat16* __restrict__ W0, const __nv_bfloat16* __restrict__ W1,
        const __nv_bfloat16* __restrict__ W2,
        const float* __restrict__ bias,
        float* __restrict__ C0, float* __restrict__ C1, float* __restrict__ C2) {
    extern __shared__ uint32_t sm[];
    const uint32_t sbase = smem_u32(sm);
    const int tid = threadIdx.x;
    const int wid = tid >> 5, lane = tid & 31;
    const int warp_m = wid >> 2, warp_n = wid & 3;
    const int g = lane >> 2, tg = lane & 3;
    const int bm = blockIdx.y * 128, bn = blockIdx.x * 128;
    const int z = blockIdx.z;
    const __nv_bfloat16* W = z == 0 ? W0 : z == 1 ? W1 : W2;
    float* C = z == 0 ? C0 : z == 1 ? C1 : C2;
    const float oscale = (TRANSV && z == 0) ? 0.125f : 1.0f;

    float acc[4][4][4];
    #pragma unroll
    for (int i = 0; i < 4; i++)
        #pragma unroll
        for (int j = 0; j < 4; j++)
            #pragma unroll
            for (int r = 0; r < 4; r++) acc[i][j][r] = 0.f;

    const int arowoff = ((lane >> 3) & 1) * 8 + (lane & 7);
    const int acbit   = (lane >> 4) & 1;
    const int browoff = ((lane >> 4) & 1) * 8 + (lane & 7);
    const int bcbit   = (lane >> 3) & 1;

    auto issue = [&](int kt, int st) {
        uint32_t abase = sbase + st * STAGE_BYTES;
        uint32_t bbase = abase + 16384;
        #pragma unroll
        for (int i = 0; i < 4; i++) {
            int ca = tid + i * 256;
            int row = ca >> 3, c4 = ca & 7;
            uint32_t doff = row * 128 + ((c4 ^ (row & 7)) << 4);
            cp16(abase + doff, A + (size_t)(bm + row) * Dc + kt * 64 + c4 * 8);
            cp16(bbase + doff, W + (size_t)(bn + row) * Dc + kt * 64 + c4 * 8);
        }
    };

    auto compute = [&](int st) {
        uint32_t abase = sbase + st * STAGE_BYTES;
        uint32_t bbase = abase + 16384;
        #pragma unroll
        for (int s = 0; s < 4; s++) {
            uint32_t af[4][4];
            #pragma unroll
            for (int i = 0; i < 4; i++) {
                int row = warp_m * 64 + i * 16 + arowoff;
                uint32_t ad = abase + row * 128 + (((2 * s + acbit) ^ (row & 7)) << 4);
                ldsm_x4(af[i][0], af[i][1], af[i][2], af[i][3], ad);
            }
            uint32_t bf[4][2];
            #pragma unroll
            for (int jp = 0; jp < 2; jp++) {
                int row = warp_n * 32 + jp * 16 + browoff;
                uint32_t bd = bbase + row * 128 + (((2 * s + bcbit) ^ (row & 7)) << 4);
                ldsm_x4(bf[2 * jp][0], bf[2 * jp][1],
                        bf[2 * jp + 1][0], bf[2 * jp + 1][1], bd);
            }
            #pragma unroll
            for (int i = 0; i < 4; i++)
                #pragma unroll
                for (int j = 0; j < 4; j++)
                    mma_bf16(acc[i][j][0], acc[i][j][1], acc[i][j][2], acc[i][j][3],
                             af[i][0], af[i][1], af[i][2], af[i][3],
                             bf[j][0], bf[j][1]);
        }
    };

    issue(0, 0); cp_commit();
    issue(1, 1); cp_commit();
    for (int kt = 0; kt < KT2; kt++) {
        cp_wait<1>();
        __syncthreads();
        int nk = kt + 2;
        if (nk < KT2) issue(nk, nk - (nk / 3) * 3);
        cp_commit();
        compute(kt - (kt / 3) * 3);
    }
    cp_wait<0>();

    if (TRANSV && z == 2) {
        __syncthreads();
        float* sf = reinterpret_cast<float*>(sm);   // [128 n][132 pad] floats
        #pragma unroll
        for (int i = 0; i < 4; i++) {
            int ml = warp_m * 64 + i * 16 + g;
            #pragma unroll
            for (int j = 0; j < 4; j++) {
                int nl = warp_n * 32 + j * 8 + tg * 2;
                float v0 = acc[i][j][0], v1 = acc[i][j][1];
                float v2 = acc[i][j][2], v3 = acc[i][j][3];
                if (ROUND) {
                    v0 = __uint_as_float(f2tf32(v0));
                    v1 = __uint_as_float(f2tf32(v1));
                    v2 = __uint_as_float(f2tf32(v2));
                    v3 = __uint_as_float(f2tf32(v3));
                }
                sf[nl * 132 + ml]           = v0;
                sf[(nl + 1) * 132 + ml]     = v1;
                sf[nl * 132 + ml + 8]       = v2;
                sf[(nl + 1) * 132 + ml + 8] = v3;
            }
        }
        __syncthreads();
        const int b_ = bm >> 10;
        const int t0 = bm & 1023;
        #pragma unroll
        for (int it = 0; it < 16; it++) {
            int idx = tid + it * 256;
            int nl = idx >> 5, m4 = (idx & 31) << 2;
            float4 vv = *reinterpret_cast<float4*>(&sf[nl * 132 + m4]);
            int h_ = (bn + nl) >> 6, dd = (bn + nl) & 63;
            float* dst = C + ((size_t)((b_ << 4) + h_) * 64 + dd) * 1024 + t0 + m4;
            *reinterpret_cast<float4*>(dst) = vv;
        }
        return;
    }

    #pragma unroll
    for (int i = 0; i < 4; i++) {
        int m0 = bm + warp_m * 64 + i * 16 + g;
        #pragma unroll
        for (int j = 0; j < 4; j++) {
            int n0 = bn + warp_n * 32 + j * 8 + tg * 2;
            float v0 = acc[i][j][0], v1 = acc[i][j][1];
            float v2 = acc[i][j][2], v3 = acc[i][j][3];
            if (BIAS) {
                float b0v = bias[n0], b1v = bias[n0 + 1];
                v0 += b0v; v1 += b1v; v2 += b0v; v3 += b1v;
            }
            if (RELU) {
                v0 = fmaxf(v0, 0.f); v1 = fmaxf(v1, 0.f);
                v2 = fmaxf(v2, 0.f); v3 = fmaxf(v3, 0.f);
            }
            if (TRANSV) { v0 *= oscale; v1 *= oscale; v2 *= oscale; v3 *= oscale; }
            if (ROUND) {
                v0 = __uint_as_float(f2tf32(v0));
                v1 = __uint_as_float(f2tf32(v1));
                v2 = __uint_as_float(f2tf32(v2));
                v3 = __uint_as_float(f2tf32(v3));
            }
            if (OBF) {
                uint32_t* Cb = reinterpret_cast<uint32_t*>(C);
                Cb[((size_t)m0 * Dc + n0) >> 1] = pack_bf16x2(v0, v1);
                Cb[((size_t)(m0 + 8) * Dc + n0) >> 1] = pack_bf16x2(v2, v3);
            } else {
                *reinterpret_cast<float2*>(&C[(size_t)m0 * Dc + n0]) = make_float2(v0, v1);
                *reinterpret_cast<float2*>(&C[(size_t)(m0 + 8) * Dc + n0]) = make_float2(v2, v3);
            }
        }
    }
}

// ======= flash attention v7: uniform no-max fast path for ALL qtiles.
//         qtile 7 runs kt0=14; row 1023 (all-masked, l=0 -> NaN) is fixed by
//         fix1023 afterwards. Single barrier per k-tile.
#define FA3_P_WORDS (128*68)
#define FA3_SMEM (65536 + FA3_P_WORDS*4)   // 100352

__global__ void __launch_bounds__(256, 2)
flash_attn7(const float* __restrict__ Qg, const float* __restrict__ Kg,
            const float* __restrict__ Vt, const float* __restrict__ maskg,
            float* __restrict__ Og) {
    extern __shared__ uint32_t sm[];
    uint32_t* sp = sm + 16384;
    const uint32_t qkvb = smem_u32(sm);

    const int tid = threadIdx.x;
    const int wid = tid >> 5;
    const int lane = tid & 31;
    const int g = lane >> 2;
    const int tg = lane & 3;
    const int arowoff = ((lane >> 3) & 1) * 8 + (lane & 7);
    const int acbit   = (lane >> 4) & 1;
    const int browoff = ((lane >> 4) & 1) * 8 + (lane & 7);
    const int bcbit   = (lane >> 3) & 1;

    const int qtile = blockIdx.x;
    const int bh = blockIdx.y;
    const int b = bh >> 4, h = bh & 15;
    const int q0 = qtile * 128;
    const size_t hb = (size_t)b * Tc * Dc + h * DHc;
    const float* vt_h = Vt + (size_t)bh * DHc * Tc;
    const int kt0 = (qtile < 7) ? 2 * qtile : 14;

    #pragma unroll
    for (int i = 0; i < 8; i++) {
        int ca = tid + i * 256;
        int row = ca >> 4, c = ca & 15;
        cp16(qkvb + sw256(row, c), Qg + hb + (size_t)(q0 + row) * Dc + c * 4);
    }
    cp_commit(); cp_wait<0>();
    __syncthreads();

    const int ra = wid * 16 + g;
    const int qa = q0 + ra, qb = qa + 8;

    uint32_t qf[8][4];
    {
        int row = wid * 16 + arowoff;
        #pragma unroll
        for (int s = 0; s < 8; s++) {
            uint32_t ad = qkvb + sw256(row, 2 * s + acbit);
            ldsm_x4(qf[s][0], qf[s][1], qf[s][2], qf[s][3], ad);
        }
    }
    __syncthreads();

    auto issue_kv = [&](int kt, int bufb) {
        uint32_t kbb = qkvb + bufb * 32768;
        uint32_t vbb = kbb + 16384;
        #pragma unroll
        for (int i = 0; i < 4; i++) {
            int ca = tid + i * 256;
            int row = ca >> 4, c = ca & 15;
            cp16(kbb + sw256(row, c), Kg + hb + (size_t)(kt * 64 + row) * Dc + c * 4);
            cp16(vbb + sw256(row, c), vt_h + (size_t)row * Tc + kt * 64 + c * 4);
        }
    };

    float l_a = 0.f, l_b = 0.f;
    float oacc[8][4];
    #pragma unroll
    for (int j = 0; j < 8; j++)
        #pragma unroll
        for (int r = 0; r < 4; r++) oacc[j][r] = 0.f;

    issue_kv(kt0, 0); cp_commit();
    int buf = 0;
    for (int kt = kt0; kt < 16; kt++) {
        cp_wait<0>();
        __syncthreads();
        if (kt + 1 < 16) { issue_kv(kt + 1, buf ^ 1); cp_commit(); }
        const uint32_t kb_s = qkvb + buf * 32768;
        const uint32_t vb_s = kb_s + 16384;

        float sacc[8][4];
        #pragma unroll
        for (int j = 0; j < 8; j++)
            #pragma unroll
            for (int r = 0; r < 4; r++) sacc[j][r] = 0.f;
        #pragma unroll
        for (int ks = 0; ks < 8; ks++) {
            uint32_t bfr[8][2];
            #pragma unroll
            for (int jp = 0; jp < 4; jp++) {
                int row = jp * 16 + browoff;
                uint32_t bd = kb_s + sw256(row, 2 * ks + bcbit);
                ldsm_x4(bfr[2 * jp][0], bfr[2 * jp][1],
                        bfr[2 * jp + 1][0], bfr[2 * jp + 1][1], bd);
            }
            #pragma unroll
            for (int j = 0; j < 8; j++)
                mma_tf32(sacc[j][0], sacc[j][1], sacc[j][2], sacc[j][3],
                         qf[ks][0], qf[ks][1], qf[ks][2], qf[ks][3],
                         bfr[j][0], bfr[j][1]);
        }

        if (kt < kt0 + 2) {
            #pragma unroll
            for (int j = 0; j < 8; j++) {
                #pragma unroll
                for (int r = 0; r < 4; r++) {
                    int col = 8 * j + 2 * tg + (r & 1);
                    int kg = kt * 64 + col;
                    int qrow = (r < 2) ? qa : qb;
                    if (kg <= qrow) sacc[j][r] -= 10000.f;
                }
            }
        }

        float rs_a = 0.f, rs_b = 0.f;
        #pragma unroll
        for (int j = 0; j < 8; j++) {
            float p0 = __expf(sacc[j][0]);
            float p1 = __expf(sacc[j][1]);
            float p2 = __expf(sacc[j][2]);
            float p3 = __expf(sacc[j][3]);
            sacc[j][0] = p0; sacc[j][1] = p1;
            sacc[j][2] = p2; sacc[j][3] = p3;
            rs_a += p0 + p1;
            rs_b += p2 + p3;
        }
        rs_a += __shfl_xor_sync(0xffffffff, rs_a, 1);
        rs_a += __shfl_xor_sync(0xffffffff, rs_a, 2);
        rs_b += __shfl_xor_sync(0xffffffff, rs_b, 1);
        rs_b += __shfl_xor_sync(0xffffffff, rs_b, 2);
        l_a += rs_a;
        l_b += rs_b;

        #pragma unroll
        for (int j = 0; j < 8; j++) {
            uint2 pa = make_uint2(f2tf32(sacc[j][0]), f2tf32(sacc[j][1]));
            uint2 pb = make_uint2(f2tf32(sacc[j][2]), f2tf32(sacc[j][3]));
            *reinterpret_cast<uint2*>(&sp[ra * 68 + 8 * j + 2 * tg]) = pa;
            *reinterpret_cast<uint2*>(&sp[(ra + 8) * 68 + 8 * j + 2 * tg]) = pb;
        }
        __syncwarp();

        #pragma unroll
        for (int s = 0; s < 8; s++) {
            uint32_t a0 = sp[ra * 68 + 8 * s + tg];
            uint32_t a1 = sp[(ra + 8) * 68 + 8 * s + tg];
            uint32_t a2 = sp[ra * 68 + 8 * s + tg + 4];
            uint32_t a3 = sp[(ra + 8) * 68 + 8 * s + tg + 4];
            uint32_t bfr[8][2];
            #pragma unroll
            for (int jp = 0; jp < 4; jp++) {
                int row = jp * 16 + browoff;
                uint32_t bd = vb_s + sw256(row, 2 * s + bcbit);
                ldsm_x4(bfr[2 * jp][0], bfr[2 * jp][1],
                        bfr[2 * jp + 1][0], bfr[2 * jp + 1][1], bd);
            }
            #pragma unroll
            for (int j = 0; j < 8; j++)
                mma_tf32(oacc[j][0], oacc[j][1], oacc[j][2], oacc[j][3],
                         a0, a1, a2, a3, bfr[j][0], bfr[j][1]);
        }
        buf ^= 1;
    }

    float sc_a = maskg[b * Tc + qa] / l_a;
    float sc_b = maskg[b * Tc + qb] / l_b;
    #pragma unroll
    for (int j = 0; j < 8; j++) {
        int col = h * DHc + 8 * j + 2 * tg;
        *reinterpret_cast<float2*>(&Og[(size_t)(b * Tc + qa) * Dc + col]) =
            make_float2(oacc[j][0] * sc_a, oacc[j][1] * sc_a);
        *reinterpret_cast<float2*>(&Og[(size_t)(b * Tc + qb) * Dc + col]) =
            make_float2(oacc[j][2] * sc_b, oacc[j][3] * sc_b);
    }
}

// ======= fix row 1023 (v2): 1024 threads, 1 key per thread, coalesced
//         warp-per-d V phase. out = softmax(s/8 - 10000) @ V, x mask.
__global__ __launch_bounds__(1024)
void fix1023(const float* __restrict__ Qg, const float* __restrict__ Kg,
             const float* __restrict__ Vt, const float* __restrict__ maskg,
             float* __restrict__ Og) {
    const int bh = blockIdx.x, b = bh >> 4, h = bh & 15;
    const int tid = threadIdx.x;
    const int w = tid >> 5, lane = tid & 31;
    __shared__ float4 qv[16];
    __shared__ float pp[1024];
    __shared__ float red[32];
    __shared__ float stot;
    const size_t hb = (size_t)b * Tc * Dc + h * DHc;
    if (tid < 16)
        qv[tid] = *reinterpret_cast<const float4*>(
            &Qg[hb + (size_t)1023 * Dc + tid * 4]);
    __syncthreads();
    // ---- score for key tid (16 independent float4 loads) ----
    const float4* kr = reinterpret_cast<const float4*>(&Kg[hb + (size_t)tid * Dc]);
    float acc = 0.f;
    #pragma unroll
    for (int j = 0; j < 16; j++) {
        float4 kv = kr[j], qq = qv[j];
        acc += kv.x * qq.x + kv.y * qq.y + kv.z * qq.z + kv.w * qq.w;
    }
    const float s = acc - 10000.f;     // reproduce reference quantization
    // ---- block max ----
    float mx = s;
    #pragma unroll
    for (int off = 16; off > 0; off >>= 1)
        mx = fmaxf(mx, __shfl_xor_sync(0xffffffffu, mx, off));
    if (lane == 0) red[w] = mx;
    __syncthreads();
    if (tid < 32) {
        float m = red[tid];
        #pragma unroll
        for (int off = 16; off > 0; off >>= 1)
            m = fmaxf(m, __shfl_xor_sync(0xffffffffu, m, off));
        if (tid == 0) red[0] = m;
    }
    __syncthreads();
    mx = red[0];
    // ---- exp + block sum ----
    float p = expf(s - mx);
    pp[tid] = p;
    float sum = p;
    #pragma unroll
    for (int off = 16; off > 0; off >>= 1)
        sum += __shfl_xor_sync(0xffffffffu, sum, off);
    __syncthreads();                   // all reads of red[0] done
    if (lane == 0) red[w] = sum;
    __syncthreads();
    if (tid < 32) {
        float ss = red[tid];
        #pragma unroll
        for (int off = 16; off > 0; off >>= 1)
            ss += __shfl_xor_sync(0xffffffffu, ss, off);
        if (tid == 0) stot = ss;
    }
    __syncthreads();
    // ---- O[d] = sum_t pp[t] * Vt[d][t]: warp w owns d = w and w+32 ----
    const float* vbase = Vt + (size_t)bh * DHc * Tc;
    const float inv = maskg[b * Tc + 1023] / stot;
    #pragma unroll
    for (int half = 0; half < 2; half++) {
        const int dd = w + half * 32;
        const float* vr = vbase + (size_t)dd * Tc;
        float a = 0.f;
        #pragma unroll
        for (int i = 0; i < 32; i++)
            a += pp[lane + i * 32] * vr[lane + i * 32];
        #pragma unroll
        for (int off = 16; off > 0; off >>= 1)
            a += __shfl_xor_sync(0xffffffffu, a, off);
        if (lane == 0)
            Og[(size_t)(b * Tc + 1023) * Dc + h * DHc + dd] = a * inv;
    }
}

// ---------- warp-per-row LN: h = LN(a + c), fp32 + bf16 copy ----------
__global__ __launch_bounds__(256)
void add_ln_w(const float* __restrict__ A, const float* __restrict__ Cv,
              const float* __restrict__ sc, const float* __restrict__ bi,
              float* __restrict__ O, uint32_t* __restrict__ Ob) {
    const int wid = threadIdx.x >> 5, lane = threadIdx.x & 31;
    const int row = blockIdx.x * 8 + wid;
    const float4* a4 = reinterpret_cast<const float4*>(A) + (size_t)row * 256;
    const float4* c4 = reinterpret_cast<const float4*>(Cv) + (size_t)row * 256;
    float4 v[8];
    float sum = 0.f, sq = 0.f;
    #pragma unroll
    for (int i = 0; i < 8; i++) {
        float4 a = a4[lane + i * 32];
        float4 c = c4[lane + i * 32];
        v[i] = make_float4(a.x + c.x, a.y + c.y, a.z + c.z, a.w + c.w);
        sum += v[i].x + v[i].y + v[i].z + v[i].w;
        sq += v[i].x * v[i].x + v[i].y * v[i].y + v[i].z * v[i].z + v[i].w * v[i].w;
    }
    #pragma unroll
    for (int off = 16; off > 0; off >>= 1) {
        sum += __shfl_xor_sync(0xffffffff, sum, off);
        sq  += __shfl_xor_sync(0xffffffff, sq, off);
    }
    float mean = sum * (1.f / Dc);
    float var = sq * (1.f / Dc) - mean * mean;
    float rs = rsqrtf(var + 1e-5f);
    #pragma unroll
    for (int i = 0; i < 8; i++) {
        int f = lane + i * 32;
        float4 s4 = reinterpret_cast<const float4*>(sc)[f];
        float4 b4 = reinterpret_cast<const float4*>(bi)[f];
        float o0 = (v[i].x - mean) * rs * s4.x + b4.x;
        float o1 = (v[i].y - mean) * rs * s4.y + b4.y;
        float o2 = (v[i].z - mean) * rs * s4.z + b4.z;
        float o3 = (v[i].w - mean) * rs * s4.w + b4.w;
        size_t gi = (size_t)row * 256 + f;
        reinterpret_cast<float4*>(O)[gi] = make_float4(o0, o1, o2, o3);
        Ob[gi * 2]     = pack_bf16x2(o0, o1);
        Ob[gi * 2 + 1] = pack_bf16x2(o2, o3);
    }
}

// ---------- warp-per-row: out = LN3(LN2(h1 + f2)) ----------
__global__ __launch_bounds__(256)
void ln2_ln3_w(const float* __restrict__ H1, const float* __restrict__ F2,
               const float* __restrict__ s2, const float* __restrict__ b2,
               const float* __restrict__ s3, const float* __restrict__ b3,
               float* __restrict__ O) {
    const int wid = threadIdx.x >> 5, lane = threadIdx.x & 31;
    const int row = blockIdx.x * 8 + wid;
    const float4* a4 = reinterpret_cast<const float4*>(H1) + (size_t)row * 256;
    const float4* c4 = reinterpret_cast<const float4*>(F2) + (size_t)row * 256;
    float4 v[8];
    float sum = 0.f, sq = 0.f;
    #pragma unroll
    for (int i = 0; i < 8; i++) {
        float4 a = a4[lane + i * 32];
        float4 c = c4[lane + i * 32];
        v[i] = make_float4(a.x + c.x, a.y + c.y, a.z + c.z, a.w + c.w);
        sum += v[i].x + v[i].y + v[i].z + v[i].w;
        sq += v[i].x * v[i].x + v[i].y * v[i].y + v[i].z * v[i].z + v[i].w * v[i].w;
    }
    #pragma unroll
    for (int off = 16; off > 0; off >>= 1) {
        sum += __shfl_xor_sync(0xffffffff, sum, off);
        sq  += __shfl_xor_sync(0xffffffff, sq, off);
    }
    float mean = sum * (1.f / Dc);
    float var = sq * (1.f / Dc) - mean * mean;
    float rs = rsqrtf(var + 1e-5f);
    sum = 0.f; sq = 0.f;
    #pragma unroll
    for (int i = 0; i < 8; i++) {
        int f = lane + i * 32;
        float4 s4 = reinterpret_cast<const float4*>(s2)[f];
        float4 b4 = reinterpret_cast<const float4*>(b2)[f];
        v[i].x = (v[i].x - mean) * rs * s4.x + b4.x;
        v[i].y = (v[i].y - mean) * rs * s4.y + b4.y;
        v[i].z = (v[i].z - mean) * rs * s4.z + b4.z;
        v[i].w = (v[i].w - mean) * rs * s4.w + b4.w;
        sum += v[i].x + v[i].y + v[i].z + v[i].w;
        sq += v[i].x * v[i].x + v[i].y * v[i].y + v[i].z * v[i].z + v[i].w * v[i].w;
    }
    #pragma unroll
    for (int off = 16; off > 0; off >>= 1) {
        sum += __shfl_xor_sync(0xffffffff, sum, off);
        sq  += __shfl_xor_sync(0xffffffff, sq, off);
    }
    float mean2 = sum * (1.f / Dc);
    float var2 = sq * (1.f / Dc) - mean2 * mean2;
    float rs2 = rsqrtf(var2 + 1e-5f);
    #pragma unroll
    for (int i = 0; i < 8; i++) {
        int f = lane + i * 32;
        float4 s4 = reinterpret_cast<const float4*>(s3)[f];
        float4 b4 = reinterpret_cast<const float4*>(b3)[f];
        float o0 = (v[i].x - mean2) * rs2 * s4.x + b4.x;
        float o1 = (v[i].y - mean2) * rs2 * s4.y + b4.y;
        float o2 = (v[i].z - mean2) * rs2 * s4.z + b4.z;
        float o3 = (v[i].w - mean2) * rs2 * s4.w + b4.w;
        reinterpret_cast<float4*>(O)[(size_t)row * 256 + f] = make_float4(o0, o1, o2, o3);
    }
}

// ---------------- launch ----------------
extern "C" void kernel_launch(void* const* d_in, const int* in_sizes, int n_in,
                              void* d_out, int out_size) {
    const float* x     = (const float*)d_in[0];
    const float* mask  = (const float*)d_in[1];
    const float* wq    = (const float*)d_in[2];
    const float* wk    = (const float*)d_in[3];
    const float* wv    = (const float*)d_in[4];
    const float* w1    = (const float*)d_in[5];
    const float* b1    = (const float*)d_in[6];
    const float* w2    = (const float*)d_in[7];
    const float* b2    = (const float*)d_in[8];
    const float* ln1s  = (const float*)d_in[9];
    const float* ln1b  = (const float*)d_in[10];
    const float* ln2s  = (const float*)d_in[11];
    const float* ln2b  = (const float*)d_in[12];
    const float* ln3s  = (const float*)d_in[13];
    const float* ln3b  = (const float*)d_in[14];
    float* out = (float*)d_out;

    float *q, *k, *vt, *att, *h1, *f2;
    uint32_t *xb, *wb, *h1b, *f1b;
    cudaGetSymbolAddress((void**)&q,   g_q);
    cudaGetSymbolAddress((void**)&k,   g_k);
    cudaGetSymbolAddress((void**)&vt,  g_vt);
    cudaGetSymbolAddress((void**)&att, g_att);
    cudaGetSymbolAddress((void**)&h1,  g_h1);
    cudaGetSymbolAddress((void**)&f2,  g_f2);
    cudaGetSymbolAddress((void**)&xb,  g_xb);
    cudaGetSymbolAddress((void**)&wb,  g_wb);
    cudaGetSymbolAddress((void**)&h1b, g_h1b);
    cudaGetSymbolAddress((void**)&f1b, g_f1b);

    cudaFuncSetAttribute(gemm_bf<false,false,true,true,false>,
                         cudaFuncAttributeMaxDynamicSharedMemorySize, GEMM2_SMEM);
    cudaFuncSetAttribute(gemm_bf<true,true,false,false,true>,
                         cudaFuncAttributeMaxDynamicSharedMemorySize, GEMM2_SMEM);
    cudaFuncSetAttribute(gemm_bf<false,true,false,false,false>,
                         cudaFuncAttributeMaxDynamicSharedMemorySize, GEMM2_SMEM);
    cudaFuncSetAttribute(flash_attn7,
                         cudaFuncAttributeMaxDynamicSharedMemorySize, FA3_SMEM);

    prep<<<9216, 256>>>(x, wq, wk, wv, w1, w2, xb, (__nv_bfloat16*)wb);

    const __nv_bfloat16* xbb = (const __nv_bfloat16*)xb;
    const __nv_bfloat16* wqb = (const __nv_bfloat16*)wb;
    const __nv_bfloat16* wkb = wqb + (size_t)1 * Dc * Dc;
    const __nv_bfloat16* wvb = wqb + (size_t)2 * Dc * Dc;
    const __nv_bfloat16* w1b = wqb + (size_t)3 * Dc * Dc;
    const __nv_bfloat16* w2b = wqb + (size_t)4 * Dc * Dc;

    gemm_bf<false,false,true,true,false><<<dim3(8, 32, 3), 256, GEMM2_SMEM>>>(
        xbb, wqb, wkb, wvb, nullptr, q, k, vt);

    flash_attn7<<<dim3(8, BHc), 256, FA3_SMEM>>>(q, k, vt, mask, att);
    fix1023<<<BHc, 1024>>>(q, k, vt, mask, att);

    add_ln_w<<<Mrows / 8, 256>>>(x, att, ln1s, ln1b, h1, h1b);

    gemm_bf<true,true,false,false,true><<<dim3(8, 32, 1), 256, GEMM2_SMEM>>>(
        (const __nv_bfloat16*)h1b, w1b, w1b, w1b, b1,
        (float*)f1b, (float*)f1b, (float*)f1b);
    gemm_bf<false,true,false,false,false><<<dim3(8, 32, 1), 256, GEMM2_SMEM>>>(
        (const __nv_bfloat16*)f1b, w2b, w2b, w2b, b2, f2, f2, f2);

    ln2_ln3_w<<<Mrows / 8, 256>>>(h1, f2, ln2s, ln2b, ln3s, ln3b, out);
}

// round 17
// speedup vs baseline: 1.1437x; 1.0210x over previous
#include <cuda_runtime.h>
#include <cuda_bf16.h>
#include <math.h>
#include <stdint.h>

#define Bc 4
#define Tc 1024
#define Dc 1024
#define Hc 16
#define DHc 64
#define Mrows (Bc*Tc)          // 4096
#define BHc (Bc*Hc)            // 64

// ---------------- static scratch (no allocations allowed) ----------------
__device__ float g_q[Mrows*Dc];
__device__ float g_k[Mrows*Dc];
__device__ float g_vt[BHc*DHc*Tc];     // V transposed per (b,h): [d][T] (tf32 bits)
__device__ float g_att[Mrows*Dc];
__device__ float g_h1[Mrows*Dc];
__device__ float g_f2[Mrows*Dc];
__device__ uint32_t g_xb[Mrows*Dc/2];  // x as bf16 pairs
__device__ uint32_t g_wb[5*Dc*Dc/2];   // transposed weights as bf16
__device__ uint32_t g_h1b[Mrows*Dc/2];
__device__ uint32_t g_f1b[Mrows*Dc/2];

__device__ __forceinline__ uint32_t f2tf32(float f) {
    uint32_t r;
    asm("cvt.rna.tf32.f32 %0, %1;" : "=r"(r) : "f"(f));
    return r;
}
__device__ __forceinline__ uint32_t pack_bf16x2(float lo, float hi) {
    uint32_t r;
    asm("cvt.rn.bf16x2.f32 %0, %1, %2;" : "=r"(r) : "f"(hi), "f"(lo));
    return r;
}
__device__ __forceinline__ uint32_t smem_u32(const void* p) {
    uint32_t a;
    asm("{ .reg .u64 t; cvta.to.shared.u64 t, %1; cvt.u32.u64 %0, t; }" : "=r"(a) : "l"(p));
    return a;
}
__device__ __forceinline__ void mma_tf32(float& d0, float& d1, float& d2, float& d3,
                                         uint32_t a0, uint32_t a1, uint32_t a2, uint32_t a3,
                                         uint32_t b0, uint32_t b1) {
    asm volatile(
        "mma.sync.aligned.m16n8k8.row.col.f32.tf32.tf32.f32 "
        "{%0,%1,%2,%3},{%4,%5,%6,%7},{%8,%9},{%0,%1,%2,%3};"
        : "+f"(d0), "+f"(d1), "+f"(d2), "+f"(d3)
        : "r"(a0), "r"(a1), "r"(a2), "r"(a3), "r"(b0), "r"(b1));
}
__device__ __forceinline__ void mma_bf16(float& d0, float& d1, float& d2, float& d3,
                                         uint32_t a0, uint32_t a1, uint32_t a2, uint32_t a3,
                                         uint32_t b0, uint32_t b1) {
    asm volatile(
        "mma.sync.aligned.m16n8k16.row.col.f32.bf16.bf16.f32 "
        "{%0,%1,%2,%3},{%4,%5,%6,%7},{%8,%9},{%0,%1,%2,%3};"
        : "+f"(d0), "+f"(d1), "+f"(d2), "+f"(d3)
        : "r"(a0), "r"(a1), "r"(a2), "r"(a3), "r"(b0), "r"(b1));
}
__device__ __forceinline__ void ldsm_x4(uint32_t& r0, uint32_t& r1, uint32_t& r2,
                                        uint32_t& r3, uint32_t addr) {
    asm volatile("ldmatrix.sync.aligned.m8n8.x4.shared.b16 {%0,%1,%2,%3}, [%4];"
                 : "=r"(r0), "=r"(r1), "=r"(r2), "=r"(r3) : "r"(addr));
}
__device__ __forceinline__ void cp16(uint32_t dst, const void* src) {
    asm volatile("cp.async.cg.shared.global [%0], [%1], 16;" :: "r"(dst), "l"(src));
}
__device__ __forceinline__ void cp_commit() {
    asm volatile("cp.async.commit_group;");
}
template<int N>
__device__ __forceinline__ void cp_wait() {
    asm volatile("cp.async.wait_group %0;" :: "n"(N));
}
__device__ __forceinline__ uint32_t sw256(int row, int c) {
    return ((uint32_t)row << 8) + (((((c & 7) ^ (row & 7)) | (c & 8)) << 4));
}

// ========== merged pre-pass: weights -> transposed bf16, x -> bf16 =========
__global__ __launch_bounds__(256)
void prep(const float* __restrict__ x,
          const float* __restrict__ wq, const float* __restrict__ wk,
          const float* __restrict__ wv, const float* __restrict__ w1,
          const float* __restrict__ w2,
          uint32_t* __restrict__ xb, __nv_bfloat16* __restrict__ wb) {
    __shared__ float t[32][33];
    const int bx = blockIdx.x;
    if (bx < 5120) {
        const int seg = bx >> 10;
        const int within = bx & 1023;
        const int nb = (within & 31) * 32;
        const int kb = (within >> 5) * 32;
        const float* src = seg == 0 ? wq : seg == 1 ? wk : seg == 2 ? wv
                          : seg == 3 ? w1 : w2;
        __nv_bfloat16* dst = wb + (size_t)seg * Dc * Dc;
        const int tx = threadIdx.x & 31;
        const int ty = threadIdx.x >> 5;
        #pragma unroll
        for (int i = 0; i < 4; i++) {
            int k = kb + ty + i * 8;
            t[ty + i * 8][tx] = src[(size_t)k * Dc + nb + tx];
        }
        __syncthreads();
        #pragma unroll
        for (int i = 0; i < 4; i++) {
            int n = nb + ty + i * 8;
            dst[(size_t)n * Dc + kb + tx] = __float2bfloat16_rn(t[tx][ty + i * 8]);
        }
    } else {
        int i = (bx - 5120) * 256 + threadIdx.x;
        float4 v = reinterpret_cast<const float4*>(x)[i];
        xb[2 * i]     = pack_bf16x2(v.x, v.y);
        xb[2 * i + 1] = pack_bf16x2(v.z, v.w);
    }
}

// ================== cp.async + ldmatrix bf16 warp-MMA GEMM =================
#define GS 3
#define STAGE_BYTES 32768
#define GEMM2_SMEM (GS*STAGE_BYTES)    // 98304
#define KT2 16                          // 1024/64

template<bool RELU, bool BIAS, bool ROUND, bool TRANSV, bool OBF>
__global__ void __launch_bounds__(256, 2)
gemm_bf(const __nv_bfloat16* __restrict__ A,
        const __nv_bfloat16* __restrict__ W0, const __nv_bfloat16* __restrict__ W1,
        const __nv_bfloat16* __restrict__ W2,
        const float* __restrict__ bias,
        float* __restrict__ C0, float* __restrict__ C1, float* __restrict__ C2) {
    extern __shared__ uint32_t sm[];
    const uint32_t sbase = smem_u32(sm);
    const int tid = threadIdx.x;
    const int wid = tid >> 5, lane = tid & 31;
    const int warp_m = wid >> 2, warp_n = wid & 3;
    const int g = lane >> 2, tg = lane & 3;
    const int bm = blockIdx.y * 128, bn = blockIdx.x * 128;
    const int z = blockIdx.z;
    const __nv_bfloat16* W = z == 0 ? W0 : z == 1 ? W1 : W2;
    float* C = z == 0 ? C0 : z == 1 ? C1 : C2;
    const float oscale = (TRANSV && z == 0) ? 0.125f : 1.0f;

    float acc[4][4][4];
    #pragma unroll
    for (int i = 0; i < 4; i++)
        #pragma unroll
        for (int j = 0; j < 4; j++)
            #pragma unroll
            for (int r = 0; r < 4; r++) acc[i][j][r] = 0.f;

    const int arowoff = ((lane >> 3) & 1) * 8 + (lane & 7);
    const int acbit   = (lane >> 4) & 1;
    const int browoff = ((lane >> 4) & 1) * 8 + (lane & 7);
    const int bcbit   = (lane >> 3) & 1;

    auto issue = [&](int kt, int st) {
        uint32_t abase = sbase + st * STAGE_BYTES;
        uint32_t bbase = abase + 16384;
        #pragma unroll
        for (int i = 0; i < 4; i++) {
            int ca = tid + i * 256;
            int row = ca >> 3, c4 = ca & 7;
            uint32_t doff = row * 128 + ((c4 ^ (row & 7)) << 4);
            cp16(abase + doff, A + (size_t)(bm + row) * Dc + kt * 64 + c4 * 8);
            cp16(bbase + doff, W + (size_t)(bn + row) * Dc + kt * 64 + c4 * 8);
        }
    };

    auto compute = [&](int st) {
        uint32_t abase = sbase + st * STAGE_BYTES;
        uint32_t bbase = abase + 16384;
        #pragma unroll
        for (int s = 0; s < 4; s++) {
            uint32_t af[4][4];
            #pragma unroll
            for (int i = 0; i < 4; i++) {
                int row = warp_m * 64 + i * 16 + arowoff;
                uint32_t ad = abase + row * 128 + (((2 * s + acbit) ^ (row & 7)) << 4);
                ldsm_x4(af[i][0], af[i][1], af[i][2], af[i][3], ad);
            }
            uint32_t bf[4][2];
            #pragma unroll
            for (int jp = 0; jp < 2; jp++) {
                int row = warp_n * 32 + jp * 16 + browoff;
                uint32_t bd = bbase + row * 128 + (((2 * s + bcbit) ^ (row & 7)) << 4);
                ldsm_x4(bf[2 * jp][0], bf[2 * jp][1],
                        bf[2 * jp + 1][0], bf[2 * jp + 1][1], bd);
            }
            #pragma unroll
            for (int i = 0; i < 4; i++)
                #pragma unroll
                for (int j = 0; j < 4; j++)
                    mma_bf16(acc[i][j][0], acc[i][j][1], acc[i][j][2], acc[i][j][3],
                             af[i][0], af[i][1], af[i][2], af[i][3],
                             bf[j][0], bf[j][1]);
        }
    };

    issue(0, 0); cp_commit();
    issue(1, 1); cp_commit();
    for (int kt = 0; kt < KT2; kt++) {
        cp_wait<1>();
        __syncthreads();
        int nk = kt + 2;
        if (nk < KT2) issue(nk, nk - (nk / 3) * 3);
        cp_commit();
        compute(kt - (kt / 3) * 3);
    }
    cp_wait<0>();

    if (TRANSV && z == 2) {
        __syncthreads();
        float* sf = reinterpret_cast<float*>(sm);   // [128 n][132 pad] floats
        #pragma unroll
        for (int i = 0; i < 4; i++) {
            int ml = warp_m * 64 + i * 16 + g;
            #pragma unroll
            for (int j = 0; j < 4; j++) {
                int nl = warp_n * 32 + j * 8 + tg * 2;
                float v0 = acc[i][j][0], v1 = acc[i][j][1];
                float v2 = acc[i][j][2], v3 = acc[i][j][3];
                if (ROUND) {
                    v0 = __uint_as_float(f2tf32(v0));
                    v1 = __uint_as_float(f2tf32(v1));
                    v2 = __uint_as_float(f2tf32(v2));
                    v3 = __uint_as_float(f2tf32(v3));
                }
                sf[nl * 132 + ml]           = v0;
                sf[(nl + 1) * 132 + ml]     = v1;
                sf[nl * 132 + ml + 8]       = v2;
                sf[(nl + 1) * 132 + ml + 8] = v3;
            }
        }
        __syncthreads();
        const int b_ = bm >> 10;
        const int t0 = bm & 1023;
        #pragma unroll
        for (int it = 0; it < 16; it++) {
            int idx = tid + it * 256;
            int nl = idx >> 5, m4 = (idx & 31) << 2;
            float4 vv = *reinterpret_cast<float4*>(&sf[nl * 132 + m4]);
            int h_ = (bn + nl) >> 6, dd = (bn + nl) & 63;
            float* dst = C + ((size_t)((b_ << 4) + h_) * 64 + dd) * 1024 + t0 + m4;
            *reinterpret_cast<float4*>(dst) = vv;
        }
        return;
    }

    #pragma unroll
    for (int i = 0; i < 4; i++) {
        int m0 = bm + warp_m * 64 + i * 16 + g;
        #pragma unroll
        for (int j = 0; j < 4; j++) {
            int n0 = bn + warp_n * 32 + j * 8 + tg * 2;
            float v0 = acc[i][j][0], v1 = acc[i][j][1];
            float v2 = acc[i][j][2], v3 = acc[i][j][3];
            if (BIAS) {
                float b0v = bias[n0], b1v = bias[n0 + 1];
                v0 += b0v; v1 += b1v; v2 += b0v; v3 += b1v;
            }
            if (RELU) {
                v0 = fmaxf(v0, 0.f); v1 = fmaxf(v1, 0.f);
                v2 = fmaxf(v2, 0.f); v3 = fmaxf(v3, 0.f);
            }
            if (TRANSV) { v0 *= oscale; v1 *= oscale; v2 *= oscale; v3 *= oscale; }
            if (ROUND) {
                v0 = __uint_as_float(f2tf32(v0));
                v1 = __uint_as_float(f2tf32(v1));
                v2 = __uint_as_float(f2tf32(v2));
                v3 = __uint_as_float(f2tf32(v3));
            }
            if (OBF) {
                uint32_t* Cb = reinterpret_cast<uint32_t*>(C);
                Cb[((size_t)m0 * Dc + n0) >> 1] = pack_bf16x2(v0, v1);
                Cb[((size_t)(m0 + 8) * Dc + n0) >> 1] = pack_bf16x2(v2, v3);
            } else {
                *reinterpret_cast<float2*>(&C[(size_t)m0 * Dc + n0]) = make_float2(v0, v1);
                *reinterpret_cast<float2*>(&C[(size_t)(m0 + 8) * Dc + n0]) = make_float2(v2, v3);
            }
        }
    }
}

// ======= flash attention v8: flash + embedded row-1023 fixer, ONE launch.
//   grid (9, 64): blockIdx.x==0 -> fixer CTA for bh=blockIdx.y;
//   x>=1 -> qtile = x-1 (no-max path; qtile 7 uses kt0=14 and SKIPS the
//   row-1023 store so the fixer owns that row; writes are disjoint).
#define FA3_P_WORDS (128*68)
#define FA3_SMEM (65536 + FA3_P_WORDS*4)   // 100352

__global__ void __launch_bounds__(256, 2)
flash_attn8(const float* __restrict__ Qg, const float* __restrict__ Kg,
            const float* __restrict__ Vt, const float* __restrict__ maskg,
            float* __restrict__ Og) {
    extern __shared__ uint32_t sm[];
    const int tid = threadIdx.x;
    const int wid = tid >> 5;
    const int lane = tid & 31;
    const int bh = blockIdx.y;
    const int b = bh >> 4, h = bh & 15;
    const size_t hb = (size_t)b * Tc * Dc + h * DHc;
    const float* vt_h = Vt + (size_t)bh * DHc * Tc;

    if (blockIdx.x == 0) {
        // ================= fixer path: row 1023 =================
        // out = softmax(s/8 - 10000) @ V (fp32 shift reproduces reference
        // quantization), x mask. 256 threads: 4 keys each.
        float4* qv = reinterpret_cast<float4*>(sm);          // 16 float4
        float* pp = reinterpret_cast<float*>(sm) + 64;       // 1024
        float* red = pp + 1024;                              // 8
        float* stot = red + 8;                               // 1
        if (tid < 16)
            qv[tid] = *reinterpret_cast<const float4*>(
                &Qg[hb + (size_t)1023 * Dc + tid * 4]);
        __syncthreads();
        float s[4]; float mx = -INFINITY;
        #pragma unroll
        for (int i = 0; i < 4; i++) {
            int t = tid + i * 256;
            const float4* kr = reinterpret_cast<const float4*>(
                &Kg[hb + (size_t)t * Dc]);
            float acc = 0.f;
            #pragma unroll
            for (int j = 0; j < 16; j++) {
                float4 kv = kr[j], qq = qv[j];
                acc += kv.x * qq.x + kv.y * qq.y + kv.z * qq.z + kv.w * qq.w;
            }
            s[i] = acc - 10000.f;
            mx = fmaxf(mx, s[i]);
        }
        #pragma unroll
        for (int off = 16; off > 0; off >>= 1)
            mx = fmaxf(mx, __shfl_xor_sync(0xffffffffu, mx, off));
        if (lane == 0) red[wid] = mx;
        __syncthreads();
        mx = red[0];
        #pragma unroll
        for (int ww = 1; ww < 8; ww++) mx = fmaxf(mx, red[ww]);
        float sum = 0.f;
        #pragma unroll
        for (int i = 0; i < 4; i++) {
            int t = tid + i * 256;
            float p = expf(s[i] - mx);
            pp[t] = p;
            sum += p;
        }
        #pragma unroll
        for (int off = 16; off > 0; off >>= 1)
            sum += __shfl_xor_sync(0xffffffffu, sum, off);
        __syncthreads();              // all reads of red (max) done
        if (lane == 0) red[wid] = sum;
        __syncthreads();
        if (tid == 0) {
            float ss = 0.f;
            for (int ww = 0; ww < 8; ww++) ss += red[ww];
            *stot = ss;
        }
        __syncthreads();
        const float inv = maskg[b * Tc + 1023] / *stot;
        #pragma unroll
        for (int dd = 0; dd < 8; dd++) {
            const int d = wid * 8 + dd;
            const float* vr = vt_h + (size_t)d * Tc;
            float a = 0.f;
            #pragma unroll
            for (int i = 0; i < 32; i++)
                a += pp[lane + i * 32] * vr[lane + i * 32];
            #pragma unroll
            for (int off = 16; off > 0; off >>= 1)
                a += __shfl_xor_sync(0xffffffffu, a, off);
            if (lane == 0)
                Og[(size_t)(b * Tc + 1023) * Dc + h * DHc + d] = a * inv;
        }
        return;
    }

    // ================= flash path =================
    uint32_t* sp = sm + 16384;
    const uint32_t qkvb = smem_u32(sm);
    const int g = lane >> 2;
    const int tg = lane & 3;
    const int arowoff = ((lane >> 3) & 1) * 8 + (lane & 7);
    const int acbit   = (lane >> 4) & 1;
    const int browoff = ((lane >> 4) & 1) * 8 + (lane & 7);
    const int bcbit   = (lane >> 3) & 1;

    const int qtile = blockIdx.x - 1;
    const int q0 = qtile * 128;
    const int kt0 = (qtile < 7) ? 2 * qtile : 14;

    #pragma unroll
    for (int i = 0; i < 8; i++) {
        int ca = tid + i * 256;
        int row = ca >> 4, c = ca & 15;
        cp16(qkvb + sw256(row, c), Qg + hb + (size_t)(q0 + row) * Dc + c * 4);
    }
    cp_commit(); cp_wait<0>();
    __syncthreads();

    const int ra = wid * 16 + g;
    const int qa = q0 + ra, qb = qa + 8;

    uint32_t qf[8][4];
    {
        int row = wid * 16 + arowoff;
        #pragma unroll
        for (int s = 0; s < 8; s++) {
            uint32_t ad = qkvb + sw256(row, 2 * s + acbit);
            ldsm_x4(qf[s][0], qf[s][1], qf[s][2], qf[s][3], ad);
        }
    }
    __syncthreads();

    auto issue_kv = [&](int kt, int bufb) {
        uint32_t kbb = qkvb + bufb * 32768;
        uint32_t vbb = kbb + 16384;
        #pragma unroll
        for (int i = 0; i < 4; i++) {
            int ca = tid + i * 256;
            int row = ca >> 4, c = ca & 15;
            cp16(kbb + sw256(row, c), Kg + hb + (size_t)(kt * 64 + row) * Dc + c * 4);
            cp16(vbb + sw256(row, c), vt_h + (size_t)row * Tc + kt * 64 + c * 4);
        }
    };

    float l_a = 0.f, l_b = 0.f;
    float oacc[8][4];
    #pragma unroll
    for (int j = 0; j < 8; j++)
        #pragma unroll
        for (int r = 0; r < 4; r++) oacc[j][r] = 0.f;

    issue_kv(kt0, 0); cp_commit();
    int buf = 0;
    for (int kt = kt0; kt < 16; kt++) {
        cp_wait<0>();
        __syncthreads();
        if (kt + 1 < 16) { issue_kv(kt + 1, buf ^ 1); cp_commit(); }
        const uint32_t kb_s = qkvb + buf * 32768;
        const uint32_t vb_s = kb_s + 16384;

        float sacc[8][4];
        #pragma unroll
        for (int j = 0; j < 8; j++)
            #pragma unroll
            for (int r = 0; r < 4; r++) sacc[j][r] = 0.f;
        #pragma unroll
        for (int ks = 0; ks < 8; ks++) {
            uint32_t bfr[8][2];
            #pragma unroll
            for (int jp = 0; jp < 4; jp++) {
                int row = jp * 16 + browoff;
                uint32_t bd = kb_s + sw256(row, 2 * ks + bcbit);
                ldsm_x4(bfr[2 * jp][0], bfr[2 * jp][1],
                        bfr[2 * jp + 1][0], bfr[2 * jp + 1][1], bd);
            }
            #pragma unroll
            for (int j = 0; j < 8; j++)
                mma_tf32(sacc[j][0], sacc[j][1], sacc[j][2], sacc[j][3],
                         qf[ks][0], qf[ks][1], qf[ks][2], qf[ks][3],
                         bfr[j][0], bfr[j][1]);
        }

        if (kt < kt0 + 2) {
            #pragma unroll
            for (int j = 0; j < 8; j++) {
                #pragma unroll
                for (int r = 0; r < 4; r++) {
                    int col = 8 * j + 2 * tg + (r & 1);
                    int kg = kt * 64 + col;
                    int qrow = (r < 2) ? qa : qb;
                    if (kg <= qrow) sacc[j][r] -= 10000.f;
                }
            }
        }

        float rs_a = 0.f, rs_b = 0.f;
        #pragma unroll
        for (int j = 0; j < 8; j++) {
            float p0 = __expf(sacc[j][0]);
            float p1 = __expf(sacc[j][1]);
            float p2 = __expf(sacc[j][2]);
            float p3 = __expf(sacc[j][3]);
            sacc[j][0] = p0; sacc[j][1] = p1;
            sacc[j][2] = p2; sacc[j][3] = p3;
            rs_a += p0 + p1;
            rs_b += p2 + p3;
        }
        rs_a += __shfl_xor_sync(0xffffffff, rs_a, 1);
        rs_a += __shfl_xor_sync(0xffffffff, rs_a, 2);
        rs_b += __shfl_xor_sync(0xffffffff, rs_b, 1);
        rs_b += __shfl_xor_sync(0xffffffff, rs_b, 2);
        l_a += rs_a;
        l_b += rs_b;

        #pragma unroll
        for (int j = 0; j < 8; j++) {
            uint2 pa = make_uint2(f2tf32(sacc[j][0]), f2tf32(sacc[j][1]));
            uint2 pb = make_uint2(f2tf32(sacc[j][2]), f2tf32(sacc[j][3]));
            *reinterpret_cast<uint2*>(&sp[ra * 68 + 8 * j + 2 * tg]) = pa;
            *reinterpret_cast<uint2*>(&sp[(ra + 8) * 68 + 8 * j + 2 * tg]) = pb;
        }
        __syncwarp();

        #pragma unroll
        for (int s = 0; s < 8; s++) {
            uint32_t a0 = sp[ra * 68 + 8 * s + tg];
            uint32_t a1 = sp[(ra + 8) * 68 + 8 * s + tg];
            uint32_t a2 = sp[ra * 68 + 8 * s + tg + 4];
            uint32_t a3 = sp[(ra + 8) * 68 + 8 * s + tg + 4];
            uint32_t bfr[8][2];
            #pragma unroll
            for (int jp = 0; jp < 4; jp++) {
                int row = jp * 16 + browoff;
                uint32_t bd = vb_s + sw256(row, 2 * s + bcbit);
                ldsm_x4(bfr[2 * jp][0], bfr[2 * jp][1],
                        bfr[2 * jp + 1][0], bfr[2 * jp + 1][1], bd);
            }
            #pragma unroll
            for (int j = 0; j < 8; j++)
                mma_tf32(oacc[j][0], oacc[j][1], oacc[j][2], oacc[j][3],
                         a0, a1, a2, a3, bfr[j][0], bfr[j][1]);
        }
        buf ^= 1;
    }

    float sc_a = maskg[b * Tc + qa] / l_a;
    float sc_b = maskg[b * Tc + qb] / l_b;
    const bool skip_b = (qb == 1023);   // fixer CTA owns row 1023
    #pragma unroll
    for (int j = 0; j < 8; j++) {
        int col = h * DHc + 8 * j + 2 * tg;
        *reinterpret_cast<float2*>(&Og[(size_t)(b * Tc + qa) * Dc + col]) =
            make_float2(oacc[j][0] * sc_a, oacc[j][1] * sc_a);
        if (!skip_b)
            *reinterpret_cast<float2*>(&Og[(size_t)(b * Tc + qb) * Dc + col]) =
                make_float2(oacc[j][2] * sc_b, oacc[j][3] * sc_b);
    }
}

// ---------- warp-per-row LN: h = LN(a + c), fp32 + bf16 copy ----------
__global__ __launch_bounds__(256)
void add_ln_w(const float* __restrict__ A, const float* __restrict__ Cv,
              const float* __restrict__ sc, const float* __restrict__ bi,
              float* __restrict__ O, uint32_t* __restrict__ Ob) {
    const int wid = threadIdx.x >> 5, lane = threadIdx.x & 31;
    const int row = blockIdx.x * 8 + wid;
    const float4* a4 = reinterpret_cast<const float4*>(A) + (size_t)row * 256;
    const float4* c4 = reinterpret_cast<const float4*>(Cv) + (size_t)row * 256;
    float4 v[8];
    float sum = 0.f, sq = 0.f;
    #pragma unroll
    for (int i = 0; i < 8; i++) {
        float4 a = a4[lane + i * 32];
        float4 c = c4[lane + i * 32];
        v[i] = make_float4(a.x + c.x, a.y + c.y, a.z + c.z, a.w + c.w);
        sum += v[i].x + v[i].y + v[i].z + v[i].w;
        sq += v[i].x * v[i].x + v[i].y * v[i].y + v[i].z * v[i].z + v[i].w * v[i].w;
    }
    #pragma unroll
    for (int off = 16; off > 0; off >>= 1) {
        sum += __shfl_xor_sync(0xffffffff, sum, off);
        sq  += __shfl_xor_sync(0xffffffff, sq, off);
    }
    float mean = sum * (1.f / Dc);
    float var = sq * (1.f / Dc) - mean * mean;
    float rs = rsqrtf(var + 1e-5f);
    #pragma unroll
    for (int i = 0; i < 8; i++) {
        int f = lane + i * 32;
        float4 s4 = reinterpret_cast<const float4*>(sc)[f];
        float4 b4 = reinterpret_cast<const float4*>(bi)[f];
        float o0 = (v[i].x - mean) * rs * s4.x + b4.x;
        float o1 = (v[i].y - mean) * rs * s4.y + b4.y;
        float o2 = (v[i].z - mean) * rs * s4.z + b4.z;
        float o3 = (v[i].w - mean) * rs * s4.w + b4.w;
        size_t gi = (size_t)row * 256 + f;
        reinterpret_cast<float4*>(O)[gi] = make_float4(o0, o1, o2, o3);
        Ob[gi * 2]     = pack_bf16x2(o0, o1);
        Ob[gi * 2 + 1] = pack_bf16x2(o2, o3);
    }
}

// ---------- warp-per-row: out = LN3(LN2(h1 + f2)) ----------
__global__ __launch_bounds__(256)
void ln2_ln3_w(const float* __restrict__ H1, const float* __restrict__ F2,
               const float* __restrict__ s2, const float* __restrict__ b2,
               const float* __restrict__ s3, const float* __restrict__ b3,
               float* __restrict__ O) {
    const int wid = threadIdx.x >> 5, lane = threadIdx.x & 31;
    const int row = blockIdx.x * 8 + wid;
    const float4* a4 = reinterpret_cast<const float4*>(H1) + (size_t)row * 256;
    const float4* c4 = reinterpret_cast<const float4*>(F2) + (size_t)row * 256;
    float4 v[8];
    float sum = 0.f, sq = 0.f;
    #pragma unroll
    for (int i = 0; i < 8; i++) {
        float4 a = a4[lane + i * 32];
        float4 c = c4[lane + i * 32];
        v[i] = make_float4(a.x + c.x, a.y + c.y, a.z + c.z, a.w + c.w);
        sum += v[i].x + v[i].y + v[i].z + v[i].w;
        sq += v[i].x * v[i].x + v[i].y * v[i].y + v[i].z * v[i].z + v[i].w * v[i].w;
    }
    #pragma unroll
    for (int off = 16; off > 0; off >>= 1) {
        sum += __shfl_xor_sync(0xffffffff, sum, off);
        sq  += __shfl_xor_sync(0xffffffff, sq, off);
    }
    float mean = sum * (1.f / Dc);
    float var = sq * (1.f / Dc) - mean * mean;
    float rs = rsqrtf(var + 1e-5f);
    sum = 0.f; sq = 0.f;
    #pragma unroll
    for (int i = 0; i < 8; i++) {
        int f = lane + i * 32;
        float4 s4 = reinterpret_cast<const float4*>(s2)[f];
        float4 b4 = reinterpret_cast<const float4*>(b2)[f];
        v[i].x = (v[i].x - mean) * rs * s4.x + b4.x;
        v[i].y = (v[i].y - mean) * rs * s4.y + b4.y;
        v[i].z = (v[i].z - mean) * rs * s4.z + b4.z;
        v[i].w = (v[i].w - mean) * rs * s4.w + b4.w;
        sum += v[i].x + v[i].y + v[i].z + v[i].w;
        sq += v[i].x * v[i].x + v[i].y * v[i].y + v[i].z * v[i].z + v[i].w * v[i].w;
    }
    #pragma unroll
    for (int off = 16; off > 0; off >>= 1) {
        sum += __shfl_xor_sync(0xffffffff, sum, off);
        sq  += __shfl_xor_sync(0xffffffff, sq, off);
    }
    float mean2 = sum * (1.f / Dc);
    float var2 = sq * (1.f / Dc) - mean2 * mean2;
    float rs2 = rsqrtf(var2 + 1e-5f);
    #pragma unroll
    for (int i = 0; i < 8; i++) {
        int f = lane + i * 32;
        float4 s4 = reinterpret_cast<const float4*>(s3)[f];
        float4 b4 = reinterpret_cast<const float4*>(b3)[f];
        float o0 = (v[i].x - mean2) * rs2 * s4.x + b4.x;
        float o1 = (v[i].y - mean2) * rs2 * s4.y + b4.y;
        float o2 = (v[i].z - mean2) * rs2 * s4.z + b4.z;
        float o3 = (v[i].w - mean2) * rs2 * s4.w + b4.w;
        reinterpret_cast<float4*>(O)[(size_t)row * 256 + f] = make_float4(o0, o1, o2, o3);
    }
}

// ---------------- launch ----------------
extern "C" void kernel_launch(void* const* d_in, const int* in_sizes, int n_in,
                              void* d_out, int out_size) {
    const float* x     = (const float*)d_in[0];
    const float* mask  = (const float*)d_in[1];
    const float* wq    = (const float*)d_in[2];
    const float* wk    = (const float*)d_in[3];
    const float* wv    = (const float*)d_in[4];
    const float* w1    = (const float*)d_in[5];
    const float* b1    = (const float*)d_in[6];
    const float* w2    = (const float*)d_in[7];
    const float* b2    = (const float*)d_in[8];
    const float* ln1s  = (const float*)d_in[9];
    const float* ln1b  = (const float*)d_in[10];
    const float* ln2s  = (const float*)d_in[11];
    const float* ln2b  = (const float*)d_in[12];
    const float* ln3s  = (const float*)d_in[13];
    const float* ln3b  = (const float*)d_in[14];
    float* out = (float*)d_out;

    float *q, *k, *vt, *att, *h1, *f2;
    uint32_t *xb, *wb, *h1b, *f1b;
    cudaGetSymbolAddress((void**)&q,   g_q);
    cudaGetSymbolAddress((void**)&k,   g_k);
    cudaGetSymbolAddress((void**)&vt,  g_vt);
    cudaGetSymbolAddress((void**)&att, g_att);
    cudaGetSymbolAddress((void**)&h1,  g_h1);
    cudaGetSymbolAddress((void**)&f2,  g_f2);
    cudaGetSymbolAddress((void**)&xb,  g_xb);
    cudaGetSymbolAddress((void**)&wb,  g_wb);
    cudaGetSymbolAddress((void**)&h1b, g_h1b);
    cudaGetSymbolAddress((void**)&f1b, g_f1b);

    cudaFuncSetAttribute(gemm_bf<false,false,true,true,false>,
                         cudaFuncAttributeMaxDynamicSharedMemorySize, GEMM2_SMEM);
    cudaFuncSetAttribute(gemm_bf<true,true,false,false,true>,
                         cudaFuncAttributeMaxDynamicSharedMemorySize, GEMM2_SMEM);
    cudaFuncSetAttribute(gemm_bf<false,true,false,false,false>,
                         cudaFuncAttributeMaxDynamicSharedMemorySize, GEMM2_SMEM);
    cudaFuncSetAttribute(flash_attn8,
                         cudaFuncAttributeMaxDynamicSharedMemorySize, FA3_SMEM);

    prep<<<9216, 256>>>(x, wq, wk, wv, w1, w2, xb, (__nv_bfloat16*)wb);

    const __nv_bfloat16* xbb = (const __nv_bfloat16*)xb;
    const __nv_bfloat16* wqb = (const __nv_bfloat16*)wb;
    const __nv_bfloat16* wkb = wqb + (size_t)1 * Dc * Dc;
    const __nv_bfloat16* wvb = wqb + (size_t)2 * Dc * Dc;
    const __nv_bfloat16* w1b = wqb + (size_t)3 * Dc * Dc;
    const __nv_bfloat16* w2b = wqb + (size_t)4 * Dc * Dc;

    gemm_bf<false,false,true,true,false><<<dim3(8, 32, 3), 256, GEMM2_SMEM>>>(
        xbb, wqb, wkb, wvb, nullptr, q, k, vt);

    flash_attn8<<<dim3(9, BHc), 256, FA3_SMEM>>>(q, k, vt, mask, att);

    add_ln_w<<<Mrows / 8, 256>>>(x, att, ln1s, ln1b, h1, h1b);

    gemm_bf<true,true,false,false,true><<<dim3(8, 32, 1), 256, GEMM2_SMEM>>>(
        (const __nv_bfloat16*)h1b, w1b, w1b, w1b, b1,
        (float*)f1b, (float*)f1b, (float*)f1b);
    gemm_bf<false,true,false,false,false><<<dim3(8, 32, 1), 256, GEMM2_SMEM>>>(
        (const __nv_bfloat16*)f1b, w2b, w2b, w2b, b2, f2, f2, f2);

    ln2_ln3_w<<<Mrows / 8, 256>>>(h1, f2, ln2s, ln2b, ln3s, ln3b, out);
}